// round 6
// baseline (speedup 1.0000x reference)
#include <cuda_runtime.h>
#include <cstddef>
#include <cstdint>

#define NN 8192
#define DD 512
#define SCALE 0.04419417382415922f   // 1/sqrt(512)

// ---------------- scratch (static __device__ — no allocs allowed) ----------
__device__ float g_q[NN * DD];
__device__ float g_k[NN * DD];
__device__ float g_v[NN * DD];
__device__ float g_sc_spill[(size_t)NN * NN / 8];     // 32 MB
__device__ unsigned int g_adj[(size_t)NN * NN / 32];  // 8 MB adjacency bitmask
__device__ float g_vpart[64 * DD];
__device__ float g_vmean[DD];
__device__ int g_is64;
// precomputed tf32 hi/lo decompositions
__device__ uint32_t g_xhi[NN * DD];
__device__ uint32_t g_xlo[NN * DD];
__device__ uint32_t g_whi[3 * DD * DD];
__device__ uint32_t g_wlo[3 * DD * DD];

// ---------------- edge dtype detection -------------------------------------
__global__ void detect_kernel(const unsigned int* __restrict__ w) {
    __shared__ unsigned int red[256];
    unsigned int acc = 0;
    for (int i = threadIdx.x; i < 1024; i += 256) acc |= w[2 * i + 1];
    red[threadIdx.x] = acc;
    __syncthreads();
    #pragma unroll
    for (int s = 128; s > 0; s >>= 1) {
        if (threadIdx.x < s) red[threadIdx.x] |= red[threadIdx.x + s];
        __syncthreads();
    }
    if (threadIdx.x == 0) g_is64 = (red[0] == 0u) ? 1 : 0;
}

// ---------------- adjacency ------------------------------------------------
__global__ void adj_zero_kernel() {
    int i = blockIdx.x * blockDim.x + threadIdx.x;
    if (i < NN * (NN / 32)) g_adj[i] = 0u;
}

__global__ void adj_scatter_kernel(const void* __restrict__ ei, int E) {
    int e = blockIdx.x * blockDim.x + threadIdx.x;
    if (e >= E) return;
    int r, c;
    if (g_is64) {
        const long long* p = (const long long*)ei;
        r = (int)p[e];
        c = (int)p[(size_t)E + e];
    } else {
        const int* p = (const int*)ei;
        r = p[e];
        c = p[(size_t)E + e];
    }
    if ((unsigned)r >= NN || (unsigned)c >= NN) return;
    size_t bit = (size_t)r * NN + (size_t)c;
    atomicOr(&g_adj[bit >> 5], 1u << (bit & 31));
}

// ---------------- tf32 helpers ---------------------------------------------
__device__ __forceinline__ uint32_t f2tf32(float x) {
    uint32_t r;
    asm("cvt.rna.tf32.f32 %0, %1;" : "=r"(r) : "f"(x));
    return r;
}

__device__ __forceinline__ void mma_tf32(float* d,
                                         const uint32_t* a,
                                         const uint32_t* b) {
    asm volatile(
        "mma.sync.aligned.m16n8k8.row.col.f32.tf32.tf32.f32 "
        "{%0,%1,%2,%3}, {%4,%5,%6,%7}, {%8,%9}, {%0,%1,%2,%3};\n"
        : "+f"(d[0]), "+f"(d[1]), "+f"(d[2]), "+f"(d[3])
        : "r"(a[0]), "r"(a[1]), "r"(a[2]), "r"(a[3]), "r"(b[0]), "r"(b[1]));
}

__device__ __forceinline__ void cp_async16(uint32_t smem_addr, const void* gptr) {
    asm volatile("cp.async.cg.shared.global [%0], [%1], 16;\n"
                 :: "r"(smem_addr), "l"(gptr));
}

// ---------------- hi/lo precompute -----------------------------------------
__global__ void conv_kernel(const float* __restrict__ src,
                            uint32_t* __restrict__ hi,
                            uint32_t* __restrict__ lo, int n4) {
    int i = blockIdx.x * 256 + threadIdx.x;
    if (i >= n4) return;
    float4 v = ((const float4*)src)[i];
    uint4 h, l;
    h.x = f2tf32(v.x); l.x = f2tf32(v.x - __uint_as_float(h.x));
    h.y = f2tf32(v.y); l.y = f2tf32(v.y - __uint_as_float(h.y));
    h.z = f2tf32(v.z); l.z = f2tf32(v.z - __uint_as_float(h.z));
    h.w = f2tf32(v.w); l.w = f2tf32(v.w - __uint_as_float(h.w));
    ((uint4*)hi)[i] = h;
    ((uint4*)lo)[i] = l;
}

// ---------------- fused QKV projection: tf32 MMA, cp.async double-buffer ---
// 128x128 C tile, BK=8, 64 stages, 256 thr = 8 warps (4 rows x 2 cols),
// warp tile 32x64. 2xTF32 split (3 MMAs), term-major for independence.
#define LDA 12      // As [m][k] row stride (8 k + 4 pad) — conflict-free frags
#define LDB 136     // Bs [k][n] row stride — conflict-free frags

__global__ __launch_bounds__(256, 2)
void proj_tf32_kernel(const float* __restrict__ bb0, float* __restrict__ o0,
                      const float* __restrict__ bb1, float* __restrict__ o1,
                      const float* __restrict__ bb2, float* __restrict__ o2)
{
    __shared__ uint32_t As_hi[2][128 * LDA];
    __shared__ uint32_t As_lo[2][128 * LDA];
    __shared__ uint32_t Bs_hi[2][8 * LDB];
    __shared__ uint32_t Bs_lo[2][8 * LDB];

    const int z = blockIdx.z;
    const float* bias;
    float* C;
    if (z == 0)      { bias = bb0; C = o0; }
    else if (z == 1) { bias = bb1; C = o1; }
    else             { bias = bb2; C = o2; }
    const uint32_t* Whi = g_whi + (size_t)z * DD * DD;
    const uint32_t* Wlo = g_wlo + (size_t)z * DD * DD;

    const int t = threadIdx.x;
    const int lane = t & 31;
    const int wid  = t >> 5;
    const int warpRow = wid >> 1;
    const int warpCol = wid & 1;
    const int g  = lane >> 2;
    const int tg = lane & 3;
    const int bm = blockIdx.y;
    const int bn = blockIdx.x;

    // loader indices (1 uint4 per array per thread per stage)
    const int a_row = t >> 1;            // 0..127
    const int a_k4  = (t & 1) * 4;       // 0 or 4
    const int b_k   = t >> 5;            // 0..7
    const int b_c   = (t & 31) * 4;      // 0..124

    const uint32_t* Axh = g_xhi + (size_t)(bm * 128 + a_row) * DD + a_k4;
    const uint32_t* Axl = g_xlo + (size_t)(bm * 128 + a_row) * DD + a_k4;
    const uint32_t* Bwh = Whi + (size_t)b_k * DD + bn * 128 + b_c;
    const uint32_t* Bwl = Wlo + (size_t)b_k * DD + bn * 128 + b_c;

    const uint32_t sAh = (uint32_t)__cvta_generic_to_shared(&As_hi[0][0]) + (a_row * LDA + a_k4) * 4;
    const uint32_t sAl = (uint32_t)__cvta_generic_to_shared(&As_lo[0][0]) + (a_row * LDA + a_k4) * 4;
    const uint32_t sBh = (uint32_t)__cvta_generic_to_shared(&Bs_hi[0][0]) + (b_k * LDB + b_c) * 4;
    const uint32_t sBl = (uint32_t)__cvta_generic_to_shared(&Bs_lo[0][0]) + (b_k * LDB + b_c) * 4;
    const uint32_t aBufStride = 128 * LDA * 4;
    const uint32_t bBufStride = 8 * LDB * 4;

    float d[2][8][4];
    #pragma unroll
    for (int mt = 0; mt < 2; mt++)
        #pragma unroll
        for (int nt = 0; nt < 8; nt++)
            #pragma unroll
            for (int r = 0; r < 4; r++) d[mt][nt][r] = 0.0f;

    // issue stage 0
    cp_async16(sAh, Axh);
    cp_async16(sAl, Axl);
    cp_async16(sBh, Bwh);
    cp_async16(sBl, Bwl);
    asm volatile("cp.async.commit_group;\n");

    const int NSTAGE = DD / 8;   // 64
    for (int s = 0; s < NSTAGE; s++) {
        const int buf = s & 1;
        if (s + 1 < NSTAGE) {
            const int kt = (s + 1) * 8;
            const int nb = buf ^ 1;
            cp_async16(sAh + nb * aBufStride, Axh + kt);
            cp_async16(sAl + nb * aBufStride, Axl + kt);
            cp_async16(sBh + nb * bBufStride, Bwh + (size_t)kt * DD);
            cp_async16(sBl + nb * bBufStride, Bwl + (size_t)kt * DD);
            asm volatile("cp.async.commit_group;\n");
            asm volatile("cp.async.wait_group 1;\n");
        } else {
            asm volatile("cp.async.wait_group 0;\n");
        }
        __syncthreads();

        // fragments for this stage
        uint32_t ahi[2][4], alo[2][4];
        #pragma unroll
        for (int mt = 0; mt < 2; mt++) {
            const int mrow = warpRow * 32 + mt * 16;
            ahi[mt][0] = As_hi[buf][(mrow + g) * LDA + tg];
            ahi[mt][1] = As_hi[buf][(mrow + g + 8) * LDA + tg];
            ahi[mt][2] = As_hi[buf][(mrow + g) * LDA + tg + 4];
            ahi[mt][3] = As_hi[buf][(mrow + g + 8) * LDA + tg + 4];
            alo[mt][0] = As_lo[buf][(mrow + g) * LDA + tg];
            alo[mt][1] = As_lo[buf][(mrow + g + 8) * LDA + tg];
            alo[mt][2] = As_lo[buf][(mrow + g) * LDA + tg + 4];
            alo[mt][3] = As_lo[buf][(mrow + g + 8) * LDA + tg + 4];
        }

        #pragma unroll
        for (int half = 0; half < 2; half++) {
            uint32_t bhi[4][2], blo[4][2];
            #pragma unroll
            for (int j = 0; j < 4; j++) {
                const int nb = warpCol * 64 + (half * 4 + j) * 8;
                bhi[j][0] = Bs_hi[buf][tg * LDB + nb + g];
                bhi[j][1] = Bs_hi[buf][(tg + 4) * LDB + nb + g];
                blo[j][0] = Bs_lo[buf][tg * LDB + nb + g];
                blo[j][1] = Bs_lo[buf][(tg + 4) * LDB + nb + g];
            }
            // term-major sweeps: 8 independent MMAs between reuses of any d
            #pragma unroll
            for (int j = 0; j < 4; j++)
                #pragma unroll
                for (int mt = 0; mt < 2; mt++)
                    mma_tf32(d[mt][half * 4 + j], ahi[mt], bhi[j]);
            #pragma unroll
            for (int j = 0; j < 4; j++)
                #pragma unroll
                for (int mt = 0; mt < 2; mt++)
                    mma_tf32(d[mt][half * 4 + j], ahi[mt], blo[j]);
            #pragma unroll
            for (int j = 0; j < 4; j++)
                #pragma unroll
                for (int mt = 0; mt < 2; mt++)
                    mma_tf32(d[mt][half * 4 + j], alo[mt], bhi[j]);
        }
        __syncthreads();
    }

    // epilogue: bias + store
    #pragma unroll
    for (int mt = 0; mt < 2; mt++) {
        const int row = bm * 128 + warpRow * 32 + mt * 16 + g;
        #pragma unroll
        for (int nt = 0; nt < 8; nt++) {
            const int col = bn * 128 + warpCol * 64 + nt * 8 + 2 * tg;
            float2 bb = *(const float2*)&bias[col];
            float2 lo = {d[mt][nt][0] + bb.x, d[mt][nt][1] + bb.y};
            float2 hi = {d[mt][nt][2] + bb.x, d[mt][nt][3] + bb.y};
            *(float2*)&C[(size_t)row * DD + col]       = lo;
            *(float2*)&C[(size_t)(row + 8) * DD + col] = hi;
        }
    }
}

// ---------------- v column mean (degree-0 rows), deterministic 2-stage -----
__global__ void vmean1_kernel() {
    const int b = blockIdx.x;
    const int t = threadIdx.x;
    float s0 = 0.f, s1 = 0.f;
    for (int r = 0; r < 128; r++) {
        const float* v = &g_v[(size_t)(b * 128 + r) * DD];
        s0 += v[t];
        s1 += v[t + 256];
    }
    g_vpart[b * DD + t] = s0;
    g_vpart[b * DD + t + 256] = s1;
}

__global__ void vmean2_kernel() {
    const int t = threadIdx.x;
    float s0 = 0.f, s1 = 0.f;
    for (int b = 0; b < 64; b++) {
        s0 += g_vpart[b * DD + t];
        s1 += g_vpart[b * DD + t + 256];
    }
    g_vmean[t]       = s0 * (1.0f / NN);
    g_vmean[t + 256] = s1 * (1.0f / NN);
}

// ---------------- sparse attention: one block (256 thr) per row -----------
#define SC_CAP 2048

__global__ __launch_bounds__(256)
void spattn_kernel(float* __restrict__ out)
{
    const int i = blockIdx.x;
    const int t = threadIdx.x;
    const int lane = t & 31;
    const int wid  = t >> 5;

    __shared__ __align__(16) float qs[DD];
    __shared__ int   nbr[NN];
    __shared__ float sc[SC_CAP];
    __shared__ int   scan[256];
    __shared__ float red[256];

    for (int d = t; d < DD; d += 256) qs[d] = g_q[(size_t)i * DD + d];

    unsigned word = g_adj[i * 256 + t];
    int pc = __popc(word);
    scan[t] = pc;
    __syncthreads();
    #pragma unroll
    for (int off = 1; off < 256; off <<= 1) {
        int mine = scan[t];
        int add  = (t >= off) ? scan[t - off] : 0;
        __syncthreads();
        scan[t] = mine + add;
        __syncthreads();
    }
    const int deg = scan[255];
    {
        int base = scan[t] - pc;
        unsigned w = word;
        while (w) {
            int b = __ffs(w) - 1;
            w &= w - 1;
            nbr[base++] = t * 32 + b;
        }
    }
    __syncthreads();

    if (deg == 0) {
        for (int d = t; d < DD; d += 256)
            out[(size_t)i * DD + d] = g_vmean[d];
        return;
    }

    float* scores = (deg <= SC_CAP) ? sc : &g_sc_spill[(size_t)i * NN / 8];

    for (int s = wid; s < deg; s += 8) {
        const float* kj = &g_k[(size_t)nbr[s] * DD];
        float acc = 0.f;
        #pragma unroll 4
        for (int d = lane; d < DD; d += 32) acc += qs[d] * kj[d];
        #pragma unroll
        for (int o = 16; o > 0; o >>= 1) acc += __shfl_xor_sync(0xffffffffu, acc, o);
        if (lane == 0) scores[s] = acc * SCALE;
    }
    __syncthreads();

    float m = -3.4e38f;
    for (int s = t; s < deg; s += 256) m = fmaxf(m, scores[s]);
    red[t] = m;
    __syncthreads();
    #pragma unroll
    for (int s = 128; s > 0; s >>= 1) {
        if (t < s) red[t] = fmaxf(red[t], red[t + s]);
        __syncthreads();
    }
    m = red[0];
    __syncthreads();

    float sum = 0.f;
    for (int s = t; s < deg; s += 256) {
        float p = __expf(scores[s] - m);
        scores[s] = p;
        sum += p;
    }
    red[t] = sum;
    __syncthreads();
    #pragma unroll
    for (int s = 128; s > 0; s >>= 1) {
        if (t < s) red[t] += red[t + s];
        __syncthreads();
    }
    const float inv = 1.0f / red[0];
    __syncthreads();

    float o0 = 0.f, o1 = 0.f;
    for (int s = 0; s < deg; s++) {
        float p = scores[s];
        const float* vj = &g_v[(size_t)nbr[s] * DD];
        o0 += p * vj[t];
        o1 += p * vj[t + 256];
    }
    out[(size_t)i * DD + t]       = o0 * inv;
    out[(size_t)i * DD + t + 256] = o1 * inv;
}

// ---------------- launch ---------------------------------------------------
extern "C" void kernel_launch(void* const* d_in, const int* in_sizes, int n_in,
                              void* d_out, int out_size)
{
    const float* x  = (const float*)d_in[0];
    const void*  ei = d_in[1];
    const float* Wq = (const float*)d_in[2];
    const float* bq = (const float*)d_in[3];
    const float* Wk = (const float*)d_in[4];
    const float* bk = (const float*)d_in[5];
    const float* Wv = (const float*)d_in[6];
    const float* bv = (const float*)d_in[7];
    float* out = (float*)d_out;
    const int E = in_sizes[1] / 2;

    float *pq, *pk, *pv;
    uint32_t *pxh, *pxl, *pwh, *pwl;
    cudaGetSymbolAddress((void**)&pq, g_q);
    cudaGetSymbolAddress((void**)&pk, g_k);
    cudaGetSymbolAddress((void**)&pv, g_v);
    cudaGetSymbolAddress((void**)&pxh, g_xhi);
    cudaGetSymbolAddress((void**)&pxl, g_xlo);
    cudaGetSymbolAddress((void**)&pwh, g_whi);
    cudaGetSymbolAddress((void**)&pwl, g_wlo);

    detect_kernel<<<1, 256>>>((const unsigned int*)ei);
    adj_zero_kernel<<<(NN * (NN / 32) + 255) / 256, 256>>>();
    adj_scatter_kernel<<<(E + 255) / 256, 256>>>(ei, E);

    // precompute tf32 hi/lo splits
    conv_kernel<<<(NN * DD / 4 + 255) / 256, 256>>>(x, pxh, pxl, NN * DD / 4);
    conv_kernel<<<(DD * DD / 4 + 255) / 256, 256>>>(Wq, pwh, pwl, DD * DD / 4);
    conv_kernel<<<(DD * DD / 4 + 255) / 256, 256>>>(Wk, pwh + DD * DD, pwl + DD * DD, DD * DD / 4);
    conv_kernel<<<(DD * DD / 4 + 255) / 256, 256>>>(Wv, pwh + 2 * DD * DD, pwl + 2 * DD * DD, DD * DD / 4);

    // fused QKV projections on tensor cores (grid.z = 3)
    dim3 gProj(DD / 128, NN / 128, 3);
    proj_tf32_kernel<<<gProj, 256>>>(bq, pq, bk, pk, bv, pv);

    vmean1_kernel<<<64, 256>>>();
    vmean2_kernel<<<1, 256>>>();

    spattn_kernel<<<NN, 256>>>(out);
}

// round 8
// speedup vs baseline: 1.3751x; 1.3751x over previous
#include <cuda_runtime.h>
#include <cuda_fp16.h>
#include <cstddef>
#include <cstdint>

#define NN 8192
#define DD 512
#define SCALE 0.04419417382415922f   // 1/sqrt(512)

// ---------------- scratch (static __device__ — no allocs allowed) ----------
__device__ float g_q[NN * DD];
__device__ float g_k[NN * DD];
__device__ float g_v[NN * DD];
__device__ float g_sc_spill[(size_t)NN * NN / 8];     // 32 MB
__device__ unsigned int g_adj[(size_t)NN * NN / 32];  // 8 MB adjacency bitmask
__device__ float g_vpart[64 * DD];
__device__ float g_vmean[DD];
__device__ int g_is64;
// fp16 hi/lo splits: x row-major [m][k]; W transposed [z][n][k]
__device__ __half g_xh[NN * DD];
__device__ __half g_xl[NN * DD];
__device__ __half g_wth[3 * DD * DD];
__device__ __half g_wtl[3 * DD * DD];

// ---------------- edge dtype detection -------------------------------------
__global__ void detect_kernel(const unsigned int* __restrict__ w) {
    __shared__ unsigned int red[256];
    unsigned int acc = 0;
    for (int i = threadIdx.x; i < 1024; i += 256) acc |= w[2 * i + 1];
    red[threadIdx.x] = acc;
    __syncthreads();
    #pragma unroll
    for (int s = 128; s > 0; s >>= 1) {
        if (threadIdx.x < s) red[threadIdx.x] |= red[threadIdx.x + s];
        __syncthreads();
    }
    if (threadIdx.x == 0) g_is64 = (red[0] == 0u) ? 1 : 0;
}

// ---------------- adjacency ------------------------------------------------
__global__ void adj_zero_kernel() {
    int i = blockIdx.x * blockDim.x + threadIdx.x;
    if (i < NN * (NN / 32)) g_adj[i] = 0u;
}

__global__ void adj_scatter_kernel(const void* __restrict__ ei, int E) {
    int e = blockIdx.x * blockDim.x + threadIdx.x;
    if (e >= E) return;
    int r, c;
    if (g_is64) {
        const long long* p = (const long long*)ei;
        r = (int)p[e];
        c = (int)p[(size_t)E + e];
    } else {
        const int* p = (const int*)ei;
        r = p[e];
        c = p[(size_t)E + e];
    }
    if ((unsigned)r >= NN || (unsigned)c >= NN) return;
    size_t bit = (size_t)r * NN + (size_t)c;
    atomicOr(&g_adj[bit >> 5], 1u << (bit & 31));
}

// ---------------- helpers ---------------------------------------------------
__device__ __forceinline__ void cp_async16(uint32_t smem_addr, const void* gptr) {
    asm volatile("cp.async.cg.shared.global [%0], [%1], 16;\n"
                 :: "r"(smem_addr), "l"(gptr));
}

__device__ __forceinline__ void ldsm_x4(uint32_t* r, uint32_t addr) {
    asm volatile("ldmatrix.sync.aligned.m8n8.x4.shared.b16 {%0,%1,%2,%3}, [%4];"
                 : "=r"(r[0]), "=r"(r[1]), "=r"(r[2]), "=r"(r[3]) : "r"(addr));
}

__device__ __forceinline__ void mma_f16(float* d, const uint32_t* a, uint32_t b0, uint32_t b1) {
    asm volatile(
        "mma.sync.aligned.m16n8k16.row.col.f32.f16.f16.f32 "
        "{%0,%1,%2,%3}, {%4,%5,%6,%7}, {%8,%9}, {%0,%1,%2,%3};\n"
        : "+f"(d[0]), "+f"(d[1]), "+f"(d[2]), "+f"(d[3])
        : "r"(a[0]), "r"(a[1]), "r"(a[2]), "r"(a[3]), "r"(b0), "r"(b1));
}

// ---------------- fp16 hi/lo precompute -------------------------------------
__global__ void convh_kernel(const float* __restrict__ src,
                             __half* __restrict__ hi,
                             __half* __restrict__ lo, int n4) {
    int i = blockIdx.x * 256 + threadIdx.x;
    if (i >= n4) return;
    float4 v = ((const float4*)src)[i];
    __half h0 = __float2half_rn(v.x), h1 = __float2half_rn(v.y);
    __half h2 = __float2half_rn(v.z), h3 = __float2half_rn(v.w);
    __half l0 = __float2half_rn(v.x - __half2float(h0));
    __half l1 = __float2half_rn(v.y - __half2float(h1));
    __half l2 = __float2half_rn(v.z - __half2float(h2));
    __half l3 = __float2half_rn(v.w - __half2float(h3));
    __half2 hp[2] = {__halves2half2(h0, h1), __halves2half2(h2, h3)};
    __half2 lp[2] = {__halves2half2(l0, l1), __halves2half2(l2, l3)};
    ((float2*)hi)[i] = *(float2*)hp;
    ((float2*)lo)[i] = *(float2*)lp;
}

// W transpose + fp16 hi/lo split: out[n][k] = W[k][n]
__global__ void convTh_kernel(const float* __restrict__ W,
                              __half* __restrict__ hi,
                              __half* __restrict__ lo) {
    __shared__ float tile[32][33];
    const int k0 = blockIdx.x * 32, n0 = blockIdx.y * 32;
    const int tx = threadIdx.x, ty = threadIdx.y;  // 32 x 8
    #pragma unroll
    for (int r = 0; r < 32; r += 8)
        tile[ty + r][tx] = W[(size_t)(k0 + ty + r) * DD + n0 + tx];
    __syncthreads();
    #pragma unroll
    for (int r = 0; r < 32; r += 8) {
        float v = tile[tx][ty + r];
        __half h = __float2half_rn(v);
        hi[(size_t)(n0 + ty + r) * DD + k0 + tx] = h;
        lo[(size_t)(n0 + ty + r) * DD + k0 + tx] = __float2half_rn(v - __half2float(h));
    }
}

// ---------------- QKV projection: fp16 mma.sync + ldmatrix ------------------
// CTA 128x128, BK=32, 256 thr = 8 warps (4x2), warp tile 32x64.
// 3-term fp16 split (hh+hl+lh). Stage = Ah|Al|Bh|Bl x 8KB = 32KB, x2 buffers.
#define PSTG 32768

__global__ void __launch_bounds__(256, 2)
proj_f16_kernel(const float* __restrict__ bq, float* __restrict__ oq,
                const float* __restrict__ bk, float* __restrict__ ok,
                const float* __restrict__ bv, float* __restrict__ ov)
{
    extern __shared__ char dsm[];
    const uint32_t sbase = (uint32_t)__cvta_generic_to_shared(dsm);

    const int z = blockIdx.z;
    const float* bias = (z == 0) ? bq : (z == 1) ? bk : bv;
    float* C          = (z == 0) ? oq : (z == 1) ? ok : ov;

    const int t = threadIdx.x;
    const int lane = t & 31;
    const int wid  = t >> 5;
    const int warpRow = wid >> 1;       // 0..3
    const int warpCol = wid & 1;        // 0..1
    const int g  = lane >> 2;
    const int tg = lane & 3;
    const int bm = blockIdx.y;
    const int bn = blockIdx.x;

    // loader: thread handles row t>>1, chunks (t&1)*2 and +1 of each tile
    const int lrow = t >> 1;
    const int lc0  = (t & 1) * 2;
    const __half* pAh = g_xh + (size_t)(bm * 128 + lrow) * DD;
    const __half* pAl = g_xl + (size_t)(bm * 128 + lrow) * DD;
    const __half* pBh = g_wth + (size_t)z * DD * DD + (size_t)(bn * 128 + lrow) * DD;
    const __half* pBl = g_wtl + (size_t)z * DD * DD + (size_t)(bn * 128 + lrow) * DD;

    // ldmatrix lane geometry
    const int rsel = (lane & 7) + ((lane >> 3) & 1) * 8;  // row within 16-row group
    const int ksel = (lane >> 4) & 1;                     // k 8-chunk select

    float d[2][8][4];
    #pragma unroll
    for (int mt = 0; mt < 2; mt++)
        #pragma unroll
        for (int nt = 0; nt < 8; nt++)
            #pragma unroll
            for (int r = 0; r < 4; r++) d[mt][nt][r] = 0.0f;

    #define LOADSTAGE(s, buf) do {                                            \
        const int _kh = (s) * 32;                                             \
        const uint32_t _sb = sbase + (buf) * PSTG;                            \
        _Pragma("unroll")                                                     \
        for (int _cc = 0; _cc < 2; _cc++) {                                   \
            const int _c = lc0 + _cc;                                         \
            const uint32_t _dst = lrow * 64 + ((_c ^ (lrow & 3)) << 4);       \
            cp_async16(_sb + _dst,         pAh + _kh + _c * 8);               \
            cp_async16(_sb + 8192 + _dst,  pAl + _kh + _c * 8);               \
            cp_async16(_sb + 16384 + _dst, pBh + _kh + _c * 8);               \
            cp_async16(_sb + 24576 + _dst, pBl + _kh + _c * 8);               \
        }                                                                     \
        asm volatile("cp.async.commit_group;\n");                             \
    } while (0)

    LOADSTAGE(0, 0);
    LOADSTAGE(1, 1);

    const int NST = DD / 32;   // 16
    for (int s = 0; s < NST; s++) {
        const int buf = s & 1;
        if (s < NST - 1) asm volatile("cp.async.wait_group 1;\n" ::: "memory");
        else             asm volatile("cp.async.wait_group 0;\n" ::: "memory");
        __syncthreads();

        const uint32_t sb = sbase + buf * PSTG;

        #pragma unroll
        for (int ks = 0; ks < 2; ks++) {
            const int chunk = ks * 2 + ksel;
            // A fragments (hi+lo) for both 16-row m tiles
            uint32_t ah[2][4], al[2][4];
            #pragma unroll
            for (int mt = 0; mt < 2; mt++) {
                const int rm = warpRow * 32 + mt * 16 + rsel;
                const uint32_t ao = sb + rm * 64 + ((chunk ^ (rm & 3)) << 4);
                ldsm_x4(ah[mt], ao);
                ldsm_x4(al[mt], ao + 8192);
            }
            #pragma unroll
            for (int half = 0; half < 2; half++) {
                // B fragments for 2 pairs (4 n-tiles)
                uint32_t bh[2][4], bl[2][4];
                #pragma unroll
                for (int p = 0; p < 2; p++) {
                    const int rn = warpCol * 64 + (half * 2 + p) * 16 + rsel;
                    const uint32_t bo = sb + 16384 + rn * 64 + ((chunk ^ (rn & 3)) << 4);
                    ldsm_x4(bh[p], bo);
                    ldsm_x4(bl[p], bo + 8192);
                }
                // term-major: 8 independent MMAs between accumulator reuse
                #pragma unroll
                for (int p = 0; p < 2; p++)
                    #pragma unroll
                    for (int sub = 0; sub < 2; sub++)
                        #pragma unroll
                        for (int mt = 0; mt < 2; mt++)
                            mma_f16(d[mt][half * 4 + p * 2 + sub], ah[mt],
                                    bh[p][sub], bh[p][sub + 2]);
                #pragma unroll
                for (int p = 0; p < 2; p++)
                    #pragma unroll
                    for (int sub = 0; sub < 2; sub++)
                        #pragma unroll
                        for (int mt = 0; mt < 2; mt++)
                            mma_f16(d[mt][half * 4 + p * 2 + sub], ah[mt],
                                    bl[p][sub], bl[p][sub + 2]);
                #pragma unroll
                for (int p = 0; p < 2; p++)
                    #pragma unroll
                    for (int sub = 0; sub < 2; sub++)
                        #pragma unroll
                        for (int mt = 0; mt < 2; mt++)
                            mma_f16(d[mt][half * 4 + p * 2 + sub], al[mt],
                                    bh[p][sub], bh[p][sub + 2]);
            }
        }
        __syncthreads();
        if (s + 2 < NST) LOADSTAGE(s + 2, buf);
    }

    // epilogue: bias + store
    #pragma unroll
    for (int mt = 0; mt < 2; mt++) {
        const int row = bm * 128 + warpRow * 32 + mt * 16 + g;
        #pragma unroll
        for (int nt = 0; nt < 8; nt++) {
            const int col = bn * 128 + warpCol * 64 + nt * 8 + 2 * tg;
            float2 bb = *(const float2*)&bias[col];
            float2 lo = {d[mt][nt][0] + bb.x, d[mt][nt][1] + bb.y};
            float2 hi = {d[mt][nt][2] + bb.x, d[mt][nt][3] + bb.y};
            *(float2*)&C[(size_t)row * DD + col]       = lo;
            *(float2*)&C[(size_t)(row + 8) * DD + col] = hi;
        }
    }
}

// ---------------- v column mean (degree-0 rows), deterministic 2-stage -----
__global__ void vmean1_kernel() {
    const int b = blockIdx.x;
    const int t = threadIdx.x;
    float s0 = 0.f, s1 = 0.f;
    for (int r = 0; r < 128; r++) {
        const float* v = &g_v[(size_t)(b * 128 + r) * DD];
        s0 += v[t];
        s1 += v[t + 256];
    }
    g_vpart[b * DD + t] = s0;
    g_vpart[b * DD + t + 256] = s1;
}

__global__ void vmean2_kernel() {
    const int t = threadIdx.x;
    float s0 = 0.f, s1 = 0.f;
    for (int b = 0; b < 64; b++) {
        s0 += g_vpart[b * DD + t];
        s1 += g_vpart[b * DD + t + 256];
    }
    g_vmean[t]       = s0 * (1.0f / NN);
    g_vmean[t + 256] = s1 * (1.0f / NN);
}

// ---------------- sparse attention: one block (256 thr) per row -----------
#define SC_CAP 2048

__global__ __launch_bounds__(256)
void spattn_kernel(float* __restrict__ out)
{
    const int i = blockIdx.x;
    const int t = threadIdx.x;
    const int lane = t & 31;
    const int wid  = t >> 5;

    __shared__ __align__(16) float qs[DD];
    __shared__ int   nbr[NN];
    __shared__ float sc[SC_CAP];
    __shared__ int   scan[256];
    __shared__ float red[256];

    for (int d = t; d < DD; d += 256) qs[d] = g_q[(size_t)i * DD + d];

    unsigned word = g_adj[i * 256 + t];
    int pc = __popc(word);
    scan[t] = pc;
    __syncthreads();
    #pragma unroll
    for (int off = 1; off < 256; off <<= 1) {
        int mine = scan[t];
        int add  = (t >= off) ? scan[t - off] : 0;
        __syncthreads();
        scan[t] = mine + add;
        __syncthreads();
    }
    const int deg = scan[255];
    {
        int base = scan[t] - pc;
        unsigned w = word;
        while (w) {
            int b = __ffs(w) - 1;
            w &= w - 1;
            nbr[base++] = t * 32 + b;
        }
    }
    __syncthreads();

    if (deg == 0) {
        for (int d = t; d < DD; d += 256)
            out[(size_t)i * DD + d] = g_vmean[d];
        return;
    }

    float* scores = (deg <= SC_CAP) ? sc : &g_sc_spill[(size_t)i * NN / 8];

    for (int s = wid; s < deg; s += 8) {
        const float* kj = &g_k[(size_t)nbr[s] * DD];
        float acc = 0.f;
        #pragma unroll 4
        for (int d = lane; d < DD; d += 32) acc += qs[d] * kj[d];
        #pragma unroll
        for (int o = 16; o > 0; o >>= 1) acc += __shfl_xor_sync(0xffffffffu, acc, o);
        if (lane == 0) scores[s] = acc * SCALE;
    }
    __syncthreads();

    float m = -3.4e38f;
    for (int s = t; s < deg; s += 256) m = fmaxf(m, scores[s]);
    red[t] = m;
    __syncthreads();
    #pragma unroll
    for (int s = 128; s > 0; s >>= 1) {
        if (t < s) red[t] = fmaxf(red[t], red[t + s]);
        __syncthreads();
    }
    m = red[0];
    __syncthreads();

    float sum = 0.f;
    for (int s = t; s < deg; s += 256) {
        float p = __expf(scores[s] - m);
        scores[s] = p;
        sum += p;
    }
    red[t] = sum;
    __syncthreads();
    #pragma unroll
    for (int s = 128; s > 0; s >>= 1) {
        if (t < s) red[t] += red[t + s];
        __syncthreads();
    }
    const float inv = 1.0f / red[0];
    __syncthreads();

    float o0 = 0.f, o1 = 0.f;
    for (int s = 0; s < deg; s++) {
        float p = scores[s];
        const float* vj = &g_v[(size_t)nbr[s] * DD];
        o0 += p * vj[t];
        o1 += p * vj[t + 256];
    }
    out[(size_t)i * DD + t]       = o0 * inv;
    out[(size_t)i * DD + t + 256] = o1 * inv;
}

// ---------------- launch ---------------------------------------------------
extern "C" void kernel_launch(void* const* d_in, const int* in_sizes, int n_in,
                              void* d_out, int out_size)
{
    const float* x  = (const float*)d_in[0];
    const void*  ei = d_in[1];
    const float* Wq = (const float*)d_in[2];
    const float* bq = (const float*)d_in[3];
    const float* Wk = (const float*)d_in[4];
    const float* bk = (const float*)d_in[5];
    const float* Wv = (const float*)d_in[6];
    const float* bv = (const float*)d_in[7];
    float* out = (float*)d_out;
    const int E = in_sizes[1] / 2;

    float *pq, *pk, *pv;
    __half *pxh, *pxl, *pwh, *pwl;
    cudaGetSymbolAddress((void**)&pq, g_q);
    cudaGetSymbolAddress((void**)&pk, g_k);
    cudaGetSymbolAddress((void**)&pv, g_v);
    cudaGetSymbolAddress((void**)&pxh, g_xh);
    cudaGetSymbolAddress((void**)&pxl, g_xl);
    cudaGetSymbolAddress((void**)&pwh, g_wth);
    cudaGetSymbolAddress((void**)&pwl, g_wtl);

    detect_kernel<<<1, 256>>>((const unsigned int*)ei);
    adj_zero_kernel<<<(NN * (NN / 32) + 255) / 256, 256>>>();
    adj_scatter_kernel<<<(E + 255) / 256, 256>>>(ei, E);

    // fp16 hi/lo precompute: x as-is, W transposed to [n][k]
    convh_kernel<<<(NN * DD / 4 + 255) / 256, 256>>>(x, pxh, pxl, NN * DD / 4);
    dim3 gT(DD / 32, DD / 32);
    dim3 bT(32, 8);
    convTh_kernel<<<gT, bT>>>(Wq, pwh, pwl);
    convTh_kernel<<<gT, bT>>>(Wk, pwh + DD * DD, pwl + DD * DD);
    convTh_kernel<<<gT, bT>>>(Wv, pwh + 2 * DD * DD, pwl + 2 * DD * DD);

    static int attr_set = 0;
    if (!attr_set) {
        cudaFuncSetAttribute(proj_f16_kernel,
                             cudaFuncAttributeMaxDynamicSharedMemorySize, 2 * PSTG);
        attr_set = 1;
    }
    dim3 gProj(DD / 128, NN / 128, 3);
    proj_f16_kernel<<<gProj, 256, 2 * PSTG>>>(bq, pq, bk, pk, bv, pv);

    vmean1_kernel<<<64, 256>>>();
    vmean2_kernel<<<1, 256>>>();

    spattn_kernel<<<NN, 256>>>(out);
}

// round 9
// speedup vs baseline: 1.4702x; 1.0691x over previous
#include <cuda_runtime.h>
#include <cuda_fp16.h>
#include <cstddef>
#include <cstdint>

#define NN 8192
#define DD 512
#define SCALE 0.04419417382415922f   // 1/sqrt(512)

// ---------------- scratch (static __device__ — no allocs allowed) ----------
__device__ float g_q[NN * DD];
__device__ float g_k[NN * DD];
__device__ float g_v[NN * DD];
__device__ float g_sc_spill[(size_t)NN * NN];         // 256 MB worst-case scores
__device__ unsigned int g_adj[(size_t)NN * NN / 32];  // 8 MB adjacency bitmask
__device__ float g_vpart[64 * DD];
__device__ float g_vmean[DD];
__device__ int g_is64;
// fp16 hi/lo splits: x row-major [m][k]; W transposed [z][n][k]
__device__ __half g_xh[NN * DD];
__device__ __half g_xl[NN * DD];
__device__ __half g_wth[3 * DD * DD];
__device__ __half g_wtl[3 * DD * DD];

// ---------------- edge dtype detection -------------------------------------
__global__ void detect_kernel(const unsigned int* __restrict__ w) {
    __shared__ unsigned int red[256];
    unsigned int acc = 0;
    for (int i = threadIdx.x; i < 1024; i += 256) acc |= w[2 * i + 1];
    red[threadIdx.x] = acc;
    __syncthreads();
    #pragma unroll
    for (int s = 128; s > 0; s >>= 1) {
        if (threadIdx.x < s) red[threadIdx.x] |= red[threadIdx.x + s];
        __syncthreads();
    }
    if (threadIdx.x == 0) g_is64 = (red[0] == 0u) ? 1 : 0;
}

// ---------------- adjacency ------------------------------------------------
__global__ void adj_zero_kernel() {
    int i = blockIdx.x * blockDim.x + threadIdx.x;
    if (i < NN * (NN / 32)) g_adj[i] = 0u;
}

__global__ void adj_scatter_kernel(const void* __restrict__ ei, int E) {
    int e = blockIdx.x * blockDim.x + threadIdx.x;
    if (e >= E) return;
    int r, c;
    if (g_is64) {
        const long long* p = (const long long*)ei;
        r = (int)p[e];
        c = (int)p[(size_t)E + e];
    } else {
        const int* p = (const int*)ei;
        r = p[e];
        c = p[(size_t)E + e];
    }
    if ((unsigned)r >= NN || (unsigned)c >= NN) return;
    size_t bit = (size_t)r * NN + (size_t)c;
    atomicOr(&g_adj[bit >> 5], 1u << (bit & 31));
}

// ---------------- helpers ---------------------------------------------------
__device__ __forceinline__ void cp_async16(uint32_t smem_addr, const void* gptr) {
    asm volatile("cp.async.cg.shared.global [%0], [%1], 16;\n"
                 :: "r"(smem_addr), "l"(gptr));
}

__device__ __forceinline__ void ldsm_x4(uint32_t* r, uint32_t addr) {
    asm volatile("ldmatrix.sync.aligned.m8n8.x4.shared.b16 {%0,%1,%2,%3}, [%4];"
                 : "=r"(r[0]), "=r"(r[1]), "=r"(r[2]), "=r"(r[3]) : "r"(addr));
}

__device__ __forceinline__ void mma_f16(float* d, const uint32_t* a, uint32_t b0, uint32_t b1) {
    asm volatile(
        "mma.sync.aligned.m16n8k16.row.col.f32.f16.f16.f32 "
        "{%0,%1,%2,%3}, {%4,%5,%6,%7}, {%8,%9}, {%0,%1,%2,%3};\n"
        : "+f"(d[0]), "+f"(d[1]), "+f"(d[2]), "+f"(d[3])
        : "r"(a[0]), "r"(a[1]), "r"(a[2]), "r"(a[3]), "r"(b0), "r"(b1));
}

// ---------------- fp16 hi/lo precompute -------------------------------------
__global__ void convh_kernel(const float* __restrict__ src,
                             __half* __restrict__ hi,
                             __half* __restrict__ lo, int n4) {
    int i = blockIdx.x * 256 + threadIdx.x;
    if (i >= n4) return;
    float4 v = ((const float4*)src)[i];
    __half h0 = __float2half_rn(v.x), h1 = __float2half_rn(v.y);
    __half h2 = __float2half_rn(v.z), h3 = __float2half_rn(v.w);
    __half l0 = __float2half_rn(v.x - __half2float(h0));
    __half l1 = __float2half_rn(v.y - __half2float(h1));
    __half l2 = __float2half_rn(v.z - __half2float(h2));
    __half l3 = __float2half_rn(v.w - __half2float(h3));
    __half2 hp[2] = {__halves2half2(h0, h1), __halves2half2(h2, h3)};
    __half2 lp[2] = {__halves2half2(l0, l1), __halves2half2(l2, l3)};
    ((float2*)hi)[i] = *(float2*)hp;
    ((float2*)lo)[i] = *(float2*)lp;
}

// W transpose + fp16 hi/lo split: out[n][k] = W[k][n]
__global__ void convTh_kernel(const float* __restrict__ W,
                              __half* __restrict__ hi,
                              __half* __restrict__ lo) {
    __shared__ float tile[32][33];
    const int k0 = blockIdx.x * 32, n0 = blockIdx.y * 32;
    const int tx = threadIdx.x, ty = threadIdx.y;  // 32 x 8
    #pragma unroll
    for (int r = 0; r < 32; r += 8)
        tile[ty + r][tx] = W[(size_t)(k0 + ty + r) * DD + n0 + tx];
    __syncthreads();
    #pragma unroll
    for (int r = 0; r < 32; r += 8) {
        float v = tile[tx][ty + r];
        __half h = __float2half_rn(v);
        hi[(size_t)(n0 + ty + r) * DD + k0 + tx] = h;
        lo[(size_t)(n0 + ty + r) * DD + k0 + tx] = __float2half_rn(v - __half2float(h));
    }
}

// ---------------- QKV projection: fp16 mma.sync + ldmatrix, 3-stage ring ----
#define PSTG 32768

__global__ void __launch_bounds__(256, 2)
proj_f16_kernel(const float* __restrict__ bq, float* __restrict__ oq,
                const float* __restrict__ bk, float* __restrict__ ok,
                const float* __restrict__ bv, float* __restrict__ ov)
{
    extern __shared__ char dsm[];
    const uint32_t sbase = (uint32_t)__cvta_generic_to_shared(dsm);

    const int z = blockIdx.z;
    const float* bias = (z == 0) ? bq : (z == 1) ? bk : bv;
    float* C          = (z == 0) ? oq : (z == 1) ? ok : ov;

    const int t = threadIdx.x;
    const int lane = t & 31;
    const int wid  = t >> 5;
    const int warpRow = wid >> 1;
    const int warpCol = wid & 1;
    const int g  = lane >> 2;
    const int tg = lane & 3;
    const int bm = blockIdx.y;
    const int bn = blockIdx.x;

    const int lrow = t >> 1;
    const int lc0  = (t & 1) * 2;
    const __half* pAh = g_xh + (size_t)(bm * 128 + lrow) * DD;
    const __half* pAl = g_xl + (size_t)(bm * 128 + lrow) * DD;
    const __half* pBh = g_wth + (size_t)z * DD * DD + (size_t)(bn * 128 + lrow) * DD;
    const __half* pBl = g_wtl + (size_t)z * DD * DD + (size_t)(bn * 128 + lrow) * DD;

    const int rsel = (lane & 7) + ((lane >> 3) & 1) * 8;
    const int ksel = (lane >> 4) & 1;

    float d[2][8][4];
    #pragma unroll
    for (int mt = 0; mt < 2; mt++)
        #pragma unroll
        for (int nt = 0; nt < 8; nt++)
            #pragma unroll
            for (int r = 0; r < 4; r++) d[mt][nt][r] = 0.0f;

    #define LOADSTAGE(s, buf) do {                                            \
        const int _kh = (s) * 32;                                             \
        const uint32_t _sb = sbase + (buf) * PSTG;                            \
        _Pragma("unroll")                                                     \
        for (int _cc = 0; _cc < 2; _cc++) {                                   \
            const int _c = lc0 + _cc;                                         \
            const uint32_t _dst = lrow * 64 + ((_c ^ (lrow & 3)) << 4);       \
            cp_async16(_sb + _dst,         pAh + _kh + _c * 8);               \
            cp_async16(_sb + 8192 + _dst,  pAl + _kh + _c * 8);               \
            cp_async16(_sb + 16384 + _dst, pBh + _kh + _c * 8);               \
            cp_async16(_sb + 24576 + _dst, pBl + _kh + _c * 8);               \
        }                                                                     \
        asm volatile("cp.async.commit_group;\n");                             \
    } while (0)

    LOADSTAGE(0, 0);
    LOADSTAGE(1, 1);

    const int NST = DD / 32;   // 16
    int buf = 0;
    for (int s = 0; s < NST; s++) {
        if (s < NST - 1) asm volatile("cp.async.wait_group 1;\n" ::: "memory");
        else             asm volatile("cp.async.wait_group 0;\n" ::: "memory");
        __syncthreads();

        // issue next loads into the third buffer before computing
        if (s + 2 < NST) {
            int nb = buf + 2; if (nb >= 3) nb -= 3;
            LOADSTAGE(s + 2, nb);
        }

        const uint32_t sb = sbase + buf * PSTG;

        #pragma unroll
        for (int ks = 0; ks < 2; ks++) {
            const int chunk = ks * 2 + ksel;
            uint32_t ah[2][4], al[2][4];
            #pragma unroll
            for (int mt = 0; mt < 2; mt++) {
                const int rm = warpRow * 32 + mt * 16 + rsel;
                const uint32_t ao = sb + rm * 64 + ((chunk ^ (rm & 3)) << 4);
                ldsm_x4(ah[mt], ao);
                ldsm_x4(al[mt], ao + 8192);
            }
            #pragma unroll
            for (int half = 0; half < 2; half++) {
                uint32_t bh[2][4], bl[2][4];
                #pragma unroll
                for (int p = 0; p < 2; p++) {
                    const int rn = warpCol * 64 + (half * 2 + p) * 16 + rsel;
                    const uint32_t bo = sb + 16384 + rn * 64 + ((chunk ^ (rn & 3)) << 4);
                    ldsm_x4(bh[p], bo);
                    ldsm_x4(bl[p], bo + 8192);
                }
                #pragma unroll
                for (int p = 0; p < 2; p++)
                    #pragma unroll
                    for (int sub = 0; sub < 2; sub++)
                        #pragma unroll
                        for (int mt = 0; mt < 2; mt++)
                            mma_f16(d[mt][half * 4 + p * 2 + sub], ah[mt],
                                    bh[p][sub], bh[p][sub + 2]);
                #pragma unroll
                for (int p = 0; p < 2; p++)
                    #pragma unroll
                    for (int sub = 0; sub < 2; sub++)
                        #pragma unroll
                        for (int mt = 0; mt < 2; mt++)
                            mma_f16(d[mt][half * 4 + p * 2 + sub], ah[mt],
                                    bl[p][sub], bl[p][sub + 2]);
                #pragma unroll
                for (int p = 0; p < 2; p++)
                    #pragma unroll
                    for (int sub = 0; sub < 2; sub++)
                        #pragma unroll
                        for (int mt = 0; mt < 2; mt++)
                            mma_f16(d[mt][half * 4 + p * 2 + sub], al[mt],
                                    bh[p][sub], bh[p][sub + 2]);
            }
        }
        buf++; if (buf == 3) buf = 0;
    }

    #pragma unroll
    for (int mt = 0; mt < 2; mt++) {
        const int row = bm * 128 + warpRow * 32 + mt * 16 + g;
        #pragma unroll
        for (int nt = 0; nt < 8; nt++) {
            const int col = bn * 128 + warpCol * 64 + nt * 8 + 2 * tg;
            float2 bb = *(const float2*)&bias[col];
            float2 lo = {d[mt][nt][0] + bb.x, d[mt][nt][1] + bb.y};
            float2 hi = {d[mt][nt][2] + bb.x, d[mt][nt][3] + bb.y};
            *(float2*)&C[(size_t)row * DD + col]       = lo;
            *(float2*)&C[(size_t)(row + 8) * DD + col] = hi;
        }
    }
}

// ---------------- v column mean (degree-0 rows), deterministic 2-stage -----
__global__ void vmean1_kernel() {
    const int b = blockIdx.x;
    const int t = threadIdx.x;
    float s0 = 0.f, s1 = 0.f;
    for (int r = 0; r < 128; r++) {
        const float* v = &g_v[(size_t)(b * 128 + r) * DD];
        s0 += v[t];
        s1 += v[t + 256];
    }
    g_vpart[b * DD + t] = s0;
    g_vpart[b * DD + t + 256] = s1;
}

__global__ void vmean2_kernel() {
    const int t = threadIdx.x;
    float s0 = 0.f, s1 = 0.f;
    for (int b = 0; b < 64; b++) {
        s0 += g_vpart[b * DD + t];
        s1 += g_vpart[b * DD + t + 256];
    }
    g_vmean[t]       = s0 * (1.0f / NN);
    g_vmean[t + 256] = s1 * (1.0f / NN);
}

// ---------------- sparse attention: one block (256 thr) per row -----------
#define SC_CAP 1024

__global__ __launch_bounds__(256)
void spattn_kernel(float* __restrict__ out)
{
    const int i = blockIdx.x;
    const int t = threadIdx.x;
    const int lane = t & 31;
    const int wid  = t >> 5;

    __shared__ __align__(16) float qs[DD];      // 2 KB
    __shared__ int   nbr[SC_CAP];               // 4 KB
    __shared__ float sc[SC_CAP];                // 4 KB
    __shared__ int   scan[256];
    __shared__ float red[256];

    for (int d = t; d < DD; d += 256) qs[d] = g_q[(size_t)i * DD + d];

    unsigned word = g_adj[i * 256 + t];
    int pc = __popc(word);
    scan[t] = pc;
    __syncthreads();
    #pragma unroll
    for (int off = 1; off < 256; off <<= 1) {
        int mine = scan[t];
        int add  = (t >= off) ? scan[t - off] : 0;
        __syncthreads();
        scan[t] = mine + add;
        __syncthreads();
    }
    const int deg = scan[255];

    if (deg == 0) {
        for (int d = t; d < DD; d += 256)
            out[(size_t)i * DD + d] = g_vmean[d];
        return;
    }

    if (deg <= SC_CAP) {
        // ---------- fast path: compact neighbor list in smem ----------
        {
            int base = scan[t] - pc;
            unsigned w = word;
            while (w) {
                int b = __ffs(w) - 1;
                w &= w - 1;
                nbr[base++] = t * 32 + b;
            }
        }
        __syncthreads();

        for (int s = wid; s < deg; s += 8) {
            const float* kj = &g_k[(size_t)nbr[s] * DD];
            float acc = 0.f;
            #pragma unroll 4
            for (int d = lane; d < DD; d += 32) acc += qs[d] * kj[d];
            #pragma unroll
            for (int o = 16; o > 0; o >>= 1) acc += __shfl_xor_sync(0xffffffffu, acc, o);
            if (lane == 0) sc[s] = acc * SCALE;
        }
        __syncthreads();

        float m = -3.4e38f;
        for (int s = t; s < deg; s += 256) m = fmaxf(m, sc[s]);
        red[t] = m;
        __syncthreads();
        #pragma unroll
        for (int s = 128; s > 0; s >>= 1) {
            if (t < s) red[t] = fmaxf(red[t], red[t + s]);
            __syncthreads();
        }
        m = red[0];
        __syncthreads();

        float sum = 0.f;
        for (int s = t; s < deg; s += 256) {
            float p = __expf(sc[s] - m);
            sc[s] = p;
            sum += p;
        }
        red[t] = sum;
        __syncthreads();
        #pragma unroll
        for (int s = 128; s > 0; s >>= 1) {
            if (t < s) red[t] += red[t + s];
            __syncthreads();
        }
        const float inv = 1.0f / red[0];
        __syncthreads();

        float o0 = 0.f, o1 = 0.f;
        int s = 0;
        for (; s + 1 < deg; s += 2) {
            float p0 = sc[s], p1 = sc[s + 1];
            const float* v0 = &g_v[(size_t)nbr[s] * DD];
            const float* v1 = &g_v[(size_t)nbr[s + 1] * DD];
            o0 += p0 * v0[t] + p1 * v1[t];
            o1 += p0 * v0[t + 256] + p1 * v1[t + 256];
        }
        if (s < deg) {
            float p = sc[s];
            const float* vj = &g_v[(size_t)nbr[s] * DD];
            o0 += p * vj[t];
            o1 += p * vj[t + 256];
        }
        out[(size_t)i * DD + t]       = o0 * inv;
        out[(size_t)i * DD + t + 256] = o1 * inv;
    } else {
        // ---------- slow path (deg > 1024, astronomically rare) ----------
        float* scores = &g_sc_spill[(size_t)i * NN];
        for (int c = wid; c < NN; c += 8) {
            bool edge = (g_adj[i * 256 + (c >> 5)] >> (c & 31)) & 1u;
            float acc = 0.f;
            if (edge) {
                const float* kj = &g_k[(size_t)c * DD];
                for (int d = lane; d < DD; d += 32) acc += qs[d] * kj[d];
                #pragma unroll
                for (int o = 16; o > 0; o >>= 1) acc += __shfl_xor_sync(0xffffffffu, acc, o);
            }
            if (lane == 0) scores[c] = edge ? acc * SCALE : -3.4e38f;
        }
        __syncthreads();

        float m = -3.4e38f;
        for (int c = t; c < NN; c += 256) m = fmaxf(m, scores[c]);
        red[t] = m;
        __syncthreads();
        #pragma unroll
        for (int s = 128; s > 0; s >>= 1) {
            if (t < s) red[t] = fmaxf(red[t], red[t + s]);
            __syncthreads();
        }
        m = red[0];
        __syncthreads();

        float sum = 0.f;
        for (int c = t; c < NN; c += 256) {
            float p = __expf(scores[c] - m);   // exp(-3.4e38 - m) = 0
            scores[c] = p;
            sum += p;
        }
        red[t] = sum;
        __syncthreads();
        #pragma unroll
        for (int s = 128; s > 0; s >>= 1) {
            if (t < s) red[t] += red[t + s];
            __syncthreads();
        }
        const float inv = 1.0f / red[0];
        __syncthreads();

        float o0 = 0.f, o1 = 0.f;
        for (int c = 0; c < NN; c++) {
            float p = scores[c];
            if (p != 0.f) {                    // uniform branch per block
                const float* vj = &g_v[(size_t)c * DD];
                o0 += p * vj[t];
                o1 += p * vj[t + 256];
            }
        }
        out[(size_t)i * DD + t]       = o0 * inv;
        out[(size_t)i * DD + t + 256] = o1 * inv;
    }
}

// ---------------- launch ---------------------------------------------------
extern "C" void kernel_launch(void* const* d_in, const int* in_sizes, int n_in,
                              void* d_out, int out_size)
{
    const float* x  = (const float*)d_in[0];
    const void*  ei = d_in[1];
    const float* Wq = (const float*)d_in[2];
    const float* bq = (const float*)d_in[3];
    const float* Wk = (const float*)d_in[4];
    const float* bk = (const float*)d_in[5];
    const float* Wv = (const float*)d_in[6];
    const float* bv = (const float*)d_in[7];
    float* out = (float*)d_out;
    const int E = in_sizes[1] / 2;

    float *pq, *pk, *pv;
    __half *pxh, *pxl, *pwh, *pwl;
    cudaGetSymbolAddress((void**)&pq, g_q);
    cudaGetSymbolAddress((void**)&pk, g_k);
    cudaGetSymbolAddress((void**)&pv, g_v);
    cudaGetSymbolAddress((void**)&pxh, g_xh);
    cudaGetSymbolAddress((void**)&pxl, g_xl);
    cudaGetSymbolAddress((void**)&pwh, g_wth);
    cudaGetSymbolAddress((void**)&pwl, g_wtl);

    static int attr_set = 0;
    if (!attr_set) {
        cudaFuncSetAttribute(proj_f16_kernel,
                             cudaFuncAttributeMaxDynamicSharedMemorySize, 3 * PSTG);
        attr_set = 1;
    }

    // launches 1-5: detect + precompute (proj is launch 6 -> ncu -s 5 profiles it)
    detect_kernel<<<1, 256>>>((const unsigned int*)ei);
    convh_kernel<<<(NN * DD / 4 + 255) / 256, 256>>>(x, pxh, pxl, NN * DD / 4);
    dim3 gT(DD / 32, DD / 32);
    dim3 bT(32, 8);
    convTh_kernel<<<gT, bT>>>(Wq, pwh, pwl);
    convTh_kernel<<<gT, bT>>>(Wk, pwh + DD * DD, pwl + DD * DD);
    convTh_kernel<<<gT, bT>>>(Wv, pwh + 2 * DD * DD, pwl + 2 * DD * DD);

    dim3 gProj(DD / 128, NN / 128, 3);
    proj_f16_kernel<<<gProj, 256, 3 * PSTG>>>(bq, pq, bk, pk, bv, pv);

    // adjacency (needed only by spattn)
    adj_zero_kernel<<<(NN * (NN / 32) + 255) / 256, 256>>>();
    adj_scatter_kernel<<<(E + 255) / 256, 256>>>(ei, E);

    vmean1_kernel<<<64, 256>>>();
    vmean2_kernel<<<1, 256>>>();

    spattn_kernel<<<NN, 256>>>(out);
}

// round 10
// speedup vs baseline: 1.5490x; 1.0536x over previous
#include <cuda_runtime.h>
#include <cuda_fp16.h>
#include <cstddef>
#include <cstdint>

#define NN 8192
#define DD 512
#define SCALE 0.04419417382415922f   // 1/sqrt(512)

// ---------------- scratch (static __device__ — no allocs allowed) ----------
__device__ float g_q[NN * DD];
__device__ float g_k[NN * DD];
__device__ float g_v[NN * DD];
__device__ float g_sc_spill[(size_t)NN * NN];         // worst-case scores
__device__ unsigned int g_adj[(size_t)NN * NN / 32];  // 8 MB adjacency bitmask
__device__ float g_vpart[64 * DD];
__device__ float g_vmean[DD];
__device__ int g_is64;
__device__ __half g_xh[NN * DD];
__device__ __half g_xl[NN * DD];
__device__ __half g_wth[3 * DD * DD];
__device__ __half g_wtl[3 * DD * DD];

// ---------------- edge dtype detection -------------------------------------
__global__ void detect_kernel(const unsigned int* __restrict__ w) {
    __shared__ unsigned int red[256];
    unsigned int acc = 0;
    for (int i = threadIdx.x; i < 1024; i += 256) acc |= w[2 * i + 1];
    red[threadIdx.x] = acc;
    __syncthreads();
    #pragma unroll
    for (int s = 128; s > 0; s >>= 1) {
        if (threadIdx.x < s) red[threadIdx.x] |= red[threadIdx.x + s];
        __syncthreads();
    }
    if (threadIdx.x == 0) g_is64 = (red[0] == 0u) ? 1 : 0;
}

// ---------------- adjacency ------------------------------------------------
__global__ void adj_zero_kernel() {
    int i = blockIdx.x * blockDim.x + threadIdx.x;
    if (i < NN * (NN / 32)) g_adj[i] = 0u;
}

__global__ void adj_scatter_kernel(const void* __restrict__ ei, int E) {
    int e = blockIdx.x * blockDim.x + threadIdx.x;
    if (e >= E) return;
    int r, c;
    if (g_is64) {
        const long long* p = (const long long*)ei;
        r = (int)p[e];
        c = (int)p[(size_t)E + e];
    } else {
        const int* p = (const int*)ei;
        r = p[e];
        c = p[(size_t)E + e];
    }
    if ((unsigned)r >= NN || (unsigned)c >= NN) return;
    size_t bit = (size_t)r * NN + (size_t)c;
    atomicOr(&g_adj[bit >> 5], 1u << (bit & 31));
}

// ---------------- helpers ---------------------------------------------------
__device__ __forceinline__ void cp_async16(uint32_t smem_addr, const void* gptr) {
    asm volatile("cp.async.cg.shared.global [%0], [%1], 16;\n"
                 :: "r"(smem_addr), "l"(gptr));
}

__device__ __forceinline__ void ldsm_x4(uint32_t* r, uint32_t addr) {
    asm volatile("ldmatrix.sync.aligned.m8n8.x4.shared.b16 {%0,%1,%2,%3}, [%4];"
                 : "=r"(r[0]), "=r"(r[1]), "=r"(r[2]), "=r"(r[3]) : "r"(addr));
}

__device__ __forceinline__ void mma_f16(float* d, const uint32_t* a, uint32_t b0, uint32_t b1) {
    asm volatile(
        "mma.sync.aligned.m16n8k16.row.col.f32.f16.f16.f32 "
        "{%0,%1,%2,%3}, {%4,%5,%6,%7}, {%8,%9}, {%0,%1,%2,%3};\n"
        : "+f"(d[0]), "+f"(d[1]), "+f"(d[2]), "+f"(d[3])
        : "r"(a[0]), "r"(a[1]), "r"(a[2]), "r"(a[3]), "r"(b0), "r"(b1));
}

// conflict-free swizzle: 16B slot = chunk ^ ((row>>1)&3)
#define SWZ(row, chunk) ((((chunk) ^ (((row) >> 1) & 3)) << 4))

// ---------------- fp16 hi/lo precompute -------------------------------------
__global__ void convh_kernel(const float* __restrict__ src,
                             __half* __restrict__ hi,
                             __half* __restrict__ lo, int n4) {
    int i = blockIdx.x * 256 + threadIdx.x;
    if (i >= n4) return;
    float4 v = ((const float4*)src)[i];
    __half h0 = __float2half_rn(v.x), h1 = __float2half_rn(v.y);
    __half h2 = __float2half_rn(v.z), h3 = __float2half_rn(v.w);
    __half l0 = __float2half_rn(v.x - __half2float(h0));
    __half l1 = __float2half_rn(v.y - __half2float(h1));
    __half l2 = __float2half_rn(v.z - __half2float(h2));
    __half l3 = __float2half_rn(v.w - __half2float(h3));
    __half2 hp[2] = {__halves2half2(h0, h1), __halves2half2(h2, h3)};
    __half2 lp[2] = {__halves2half2(l0, l1), __halves2half2(l2, l3)};
    ((float2*)hi)[i] = *(float2*)hp;
    ((float2*)lo)[i] = *(float2*)lp;
}

// fused: W transpose + fp16 hi/lo split for all 3 weights (grid.z selects)
__global__ void convTh3_kernel(const float* __restrict__ Wq,
                               const float* __restrict__ Wk,
                               const float* __restrict__ Wv) {
    const int z = blockIdx.z;
    const float* W = (z == 0) ? Wq : (z == 1) ? Wk : Wv;
    __half* hi = g_wth + (size_t)z * DD * DD;
    __half* lo = g_wtl + (size_t)z * DD * DD;

    __shared__ float tile[32][33];
    const int k0 = blockIdx.x * 32, n0 = blockIdx.y * 32;
    const int tx = threadIdx.x, ty = threadIdx.y;  // 32 x 8
    #pragma unroll
    for (int r = 0; r < 32; r += 8)
        tile[ty + r][tx] = W[(size_t)(k0 + ty + r) * DD + n0 + tx];
    __syncthreads();
    #pragma unroll
    for (int r = 0; r < 32; r += 8) {
        float v = tile[tx][ty + r];
        __half h = __float2half_rn(v);
        hi[(size_t)(n0 + ty + r) * DD + k0 + tx] = h;
        lo[(size_t)(n0 + ty + r) * DD + k0 + tx] = __float2half_rn(v - __half2float(h));
    }
}

// ---------------- QKV projection: fp16 mma.sync + ldmatrix, 3-stage ring ----
#define PSTG 32768

__global__ void __launch_bounds__(256, 2)
proj_f16_kernel(const float* __restrict__ bq, float* __restrict__ oq,
                const float* __restrict__ bk, float* __restrict__ ok,
                const float* __restrict__ bv, float* __restrict__ ov)
{
    extern __shared__ char dsm[];
    const uint32_t sbase = (uint32_t)__cvta_generic_to_shared(dsm);

    const int z = blockIdx.z;
    const float* bias = (z == 0) ? bq : (z == 1) ? bk : bv;
    float* C          = (z == 0) ? oq : (z == 1) ? ok : ov;

    const int t = threadIdx.x;
    const int lane = t & 31;
    const int wid  = t >> 5;
    const int warpRow = wid >> 1;
    const int warpCol = wid & 1;
    const int g  = lane >> 2;
    const int tg = lane & 3;
    const int bm = blockIdx.y;
    const int bn = blockIdx.x;

    const int lrow = t >> 1;
    const int lc0  = (t & 1) * 2;
    const __half* pAh = g_xh + (size_t)(bm * 128 + lrow) * DD;
    const __half* pAl = g_xl + (size_t)(bm * 128 + lrow) * DD;
    const __half* pBh = g_wth + (size_t)z * DD * DD + (size_t)(bn * 128 + lrow) * DD;
    const __half* pBl = g_wtl + (size_t)z * DD * DD + (size_t)(bn * 128 + lrow) * DD;

    const int rsel = (lane & 7) + ((lane >> 3) & 1) * 8;
    const int ksel = (lane >> 4) & 1;

    float d[2][8][4];
    #pragma unroll
    for (int mt = 0; mt < 2; mt++)
        #pragma unroll
        for (int nt = 0; nt < 8; nt++)
            #pragma unroll
            for (int r = 0; r < 4; r++) d[mt][nt][r] = 0.0f;

    #define LOADSTAGE(s, buf) do {                                            \
        const int _kh = (s) * 32;                                             \
        const uint32_t _sb = sbase + (buf) * PSTG;                            \
        _Pragma("unroll")                                                     \
        for (int _cc = 0; _cc < 2; _cc++) {                                   \
            const int _c = lc0 + _cc;                                         \
            const uint32_t _dst = lrow * 64 + SWZ(lrow, _c);                  \
            cp_async16(_sb + _dst,         pAh + _kh + _c * 8);               \
            cp_async16(_sb + 8192 + _dst,  pAl + _kh + _c * 8);               \
            cp_async16(_sb + 16384 + _dst, pBh + _kh + _c * 8);               \
            cp_async16(_sb + 24576 + _dst, pBl + _kh + _c * 8);               \
        }                                                                     \
        asm volatile("cp.async.commit_group;\n");                             \
    } while (0)

    LOADSTAGE(0, 0);
    LOADSTAGE(1, 1);

    const int NST = DD / 32;   // 16
    int buf = 0;
    for (int s = 0; s < NST; s++) {
        if (s < NST - 1) asm volatile("cp.async.wait_group 1;\n" ::: "memory");
        else             asm volatile("cp.async.wait_group 0;\n" ::: "memory");
        __syncthreads();

        if (s + 2 < NST) {
            int nb = buf + 2; if (nb >= 3) nb -= 3;
            LOADSTAGE(s + 2, nb);
        }

        const uint32_t sb = sbase + buf * PSTG;

        #pragma unroll
        for (int ks = 0; ks < 2; ks++) {
            const int chunk = ks * 2 + ksel;
            uint32_t ah[2][4], al[2][4];
            #pragma unroll
            for (int mt = 0; mt < 2; mt++) {
                const int rm = warpRow * 32 + mt * 16 + rsel;
                const uint32_t ao = sb + rm * 64 + SWZ(rm, chunk);
                ldsm_x4(ah[mt], ao);
                ldsm_x4(al[mt], ao + 8192);
            }
            #pragma unroll
            for (int half = 0; half < 2; half++) {
                uint32_t bh[2][4], bl[2][4];
                #pragma unroll
                for (int p = 0; p < 2; p++) {
                    const int rn = warpCol * 64 + (half * 2 + p) * 16 + rsel;
                    const uint32_t bo = sb + 16384 + rn * 64 + SWZ(rn, chunk);
                    ldsm_x4(bh[p], bo);
                    ldsm_x4(bl[p], bo + 8192);
                }
                #pragma unroll
                for (int p = 0; p < 2; p++)
                    #pragma unroll
                    for (int sub = 0; sub < 2; sub++)
                        #pragma unroll
                        for (int mt = 0; mt < 2; mt++)
                            mma_f16(d[mt][half * 4 + p * 2 + sub], ah[mt],
                                    bh[p][sub], bh[p][sub + 2]);
                #pragma unroll
                for (int p = 0; p < 2; p++)
                    #pragma unroll
                    for (int sub = 0; sub < 2; sub++)
                        #pragma unroll
                        for (int mt = 0; mt < 2; mt++)
                            mma_f16(d[mt][half * 4 + p * 2 + sub], ah[mt],
                                    bl[p][sub], bl[p][sub + 2]);
                #pragma unroll
                for (int p = 0; p < 2; p++)
                    #pragma unroll
                    for (int sub = 0; sub < 2; sub++)
                        #pragma unroll
                        for (int mt = 0; mt < 2; mt++)
                            mma_f16(d[mt][half * 4 + p * 2 + sub], al[mt],
                                    bh[p][sub], bh[p][sub + 2]);
            }
        }
        buf++; if (buf == 3) buf = 0;
    }

    #pragma unroll
    for (int mt = 0; mt < 2; mt++) {
        const int row = bm * 128 + warpRow * 32 + mt * 16 + g;
        #pragma unroll
        for (int nt = 0; nt < 8; nt++) {
            const int col = bn * 128 + warpCol * 64 + nt * 8 + 2 * tg;
            float2 bb = *(const float2*)&bias[col];
            float2 lo = {d[mt][nt][0] + bb.x, d[mt][nt][1] + bb.y};
            float2 hi = {d[mt][nt][2] + bb.x, d[mt][nt][3] + bb.y};
            *(float2*)&C[(size_t)row * DD + col]       = lo;
            *(float2*)&C[(size_t)(row + 8) * DD + col] = hi;
        }
    }
}

// ---------------- v column mean (degree-0 rows), deterministic 2-stage -----
__global__ void vmean1_kernel() {
    const int b = blockIdx.x;
    const int t = threadIdx.x;
    float s0 = 0.f, s1 = 0.f;
    for (int r = 0; r < 128; r++) {
        const float* v = &g_v[(size_t)(b * 128 + r) * DD];
        s0 += v[t];
        s1 += v[t + 256];
    }
    g_vpart[b * DD + t] = s0;
    g_vpart[b * DD + t + 256] = s1;
}

__global__ void vmean2_kernel() {
    const int t = threadIdx.x;
    float s0 = 0.f, s1 = 0.f;
    for (int b = 0; b < 64; b++) {
        s0 += g_vpart[b * DD + t];
        s1 += g_vpart[b * DD + t + 256];
    }
    g_vmean[t]       = s0 * (1.0f / NN);
    g_vmean[t + 256] = s1 * (1.0f / NN);
}

// ---------------- sparse attention: one block (256 thr) per row -----------
#define SC_CAP 1024

__global__ __launch_bounds__(256)
void spattn_kernel(float* __restrict__ out)
{
    const int i = blockIdx.x;
    const int t = threadIdx.x;
    const int lane = t & 31;
    const int wid  = t >> 5;

    __shared__ __align__(16) float qs[DD];
    __shared__ int   nbr[SC_CAP];
    __shared__ float sc[SC_CAP];
    __shared__ int   scan[256];
    __shared__ float red[256];

    for (int d = t; d < DD; d += 256) qs[d] = g_q[(size_t)i * DD + d];

    unsigned word = g_adj[i * 256 + t];
    int pc = __popc(word);
    scan[t] = pc;
    __syncthreads();
    #pragma unroll
    for (int off = 1; off < 256; off <<= 1) {
        int mine = scan[t];
        int add  = (t >= off) ? scan[t - off] : 0;
        __syncthreads();
        scan[t] = mine + add;
        __syncthreads();
    }
    const int deg = scan[255];

    if (deg == 0) {
        for (int d = t; d < DD; d += 256)
            out[(size_t)i * DD + d] = g_vmean[d];
        return;
    }

    if (deg <= SC_CAP) {
        {
            int base = scan[t] - pc;
            unsigned w = word;
            while (w) {
                int b = __ffs(w) - 1;
                w &= w - 1;
                nbr[base++] = t * 32 + b;
            }
        }
        __syncthreads();

        for (int s = wid; s < deg; s += 8) {
            const float* kj = &g_k[(size_t)nbr[s] * DD];
            float acc = 0.f;
            #pragma unroll 4
            for (int d = lane; d < DD; d += 32) acc += qs[d] * kj[d];
            #pragma unroll
            for (int o = 16; o > 0; o >>= 1) acc += __shfl_xor_sync(0xffffffffu, acc, o);
            if (lane == 0) sc[s] = acc * SCALE;
        }
        __syncthreads();

        float m = -3.4e38f;
        for (int s = t; s < deg; s += 256) m = fmaxf(m, sc[s]);
        red[t] = m;
        __syncthreads();
        #pragma unroll
        for (int s = 128; s > 0; s >>= 1) {
            if (t < s) red[t] = fmaxf(red[t], red[t + s]);
            __syncthreads();
        }
        m = red[0];
        __syncthreads();

        float sum = 0.f;
        for (int s = t; s < deg; s += 256) {
            float p = __expf(sc[s] - m);
            sc[s] = p;
            sum += p;
        }
        red[t] = sum;
        __syncthreads();
        #pragma unroll
        for (int s = 128; s > 0; s >>= 1) {
            if (t < s) red[t] += red[t + s];
            __syncthreads();
        }
        const float inv = 1.0f / red[0];
        __syncthreads();

        float o0 = 0.f, o1 = 0.f;
        int s = 0;
        for (; s + 1 < deg; s += 2) {
            float p0 = sc[s], p1 = sc[s + 1];
            const float* v0 = &g_v[(size_t)nbr[s] * DD];
            const float* v1 = &g_v[(size_t)nbr[s + 1] * DD];
            o0 += p0 * v0[t] + p1 * v1[t];
            o1 += p0 * v0[t + 256] + p1 * v1[t + 256];
        }
        if (s < deg) {
            float p = sc[s];
            const float* vj = &g_v[(size_t)nbr[s] * DD];
            o0 += p * vj[t];
            o1 += p * vj[t + 256];
        }
        out[(size_t)i * DD + t]       = o0 * inv;
        out[(size_t)i * DD + t + 256] = o1 * inv;
    } else {
        float* scores = &g_sc_spill[(size_t)i * NN];
        for (int c = wid; c < NN; c += 8) {
            bool edge = (g_adj[i * 256 + (c >> 5)] >> (c & 31)) & 1u;
            float acc = 0.f;
            if (edge) {
                const float* kj = &g_k[(size_t)c * DD];
                for (int d = lane; d < DD; d += 32) acc += qs[d] * kj[d];
                #pragma unroll
                for (int o = 16; o > 0; o >>= 1) acc += __shfl_xor_sync(0xffffffffu, acc, o);
            }
            if (lane == 0) scores[c] = edge ? acc * SCALE : -3.4e38f;
        }
        __syncthreads();

        float m = -3.4e38f;
        for (int c = t; c < NN; c += 256) m = fmaxf(m, scores[c]);
        red[t] = m;
        __syncthreads();
        #pragma unroll
        for (int s = 128; s > 0; s >>= 1) {
            if (t < s) red[t] = fmaxf(red[t], red[t + s]);
            __syncthreads();
        }
        m = red[0];
        __syncthreads();

        float sum = 0.f;
        for (int c = t; c < NN; c += 256) {
            float p = __expf(scores[c] - m);
            scores[c] = p;
            sum += p;
        }
        red[t] = sum;
        __syncthreads();
        #pragma unroll
        for (int s = 128; s > 0; s >>= 1) {
            if (t < s) red[t] += red[t + s];
            __syncthreads();
        }
        const float inv = 1.0f / red[0];
        __syncthreads();

        float o0 = 0.f, o1 = 0.f;
        for (int c = 0; c < NN; c++) {
            float p = scores[c];
            if (p != 0.f) {
                const float* vj = &g_v[(size_t)c * DD];
                o0 += p * vj[t];
                o1 += p * vj[t + 256];
            }
        }
        out[(size_t)i * DD + t]       = o0 * inv;
        out[(size_t)i * DD + t + 256] = o1 * inv;
    }
}

// ---------------- launch ---------------------------------------------------
extern "C" void kernel_launch(void* const* d_in, const int* in_sizes, int n_in,
                              void* d_out, int out_size)
{
    const float* x  = (const float*)d_in[0];
    const void*  ei = d_in[1];
    const float* Wq = (const float*)d_in[2];
    const float* bq = (const float*)d_in[3];
    const float* Wk = (const float*)d_in[4];
    const float* bk = (const float*)d_in[5];
    const float* Wv = (const float*)d_in[6];
    const float* bv = (const float*)d_in[7];
    float* out = (float*)d_out;
    const int E = in_sizes[1] / 2;

    float *pq, *pk, *pv;
    __half *pxh, *pxl;
    cudaGetSymbolAddress((void**)&pq, g_q);
    cudaGetSymbolAddress((void**)&pk, g_k);
    cudaGetSymbolAddress((void**)&pv, g_v);
    cudaGetSymbolAddress((void**)&pxh, g_xh);
    cudaGetSymbolAddress((void**)&pxl, g_xl);

    static cudaStream_t s2 = nullptr;
    static cudaEvent_t evFork = nullptr, evJoin = nullptr;
    if (!s2) {
        cudaStreamCreateWithFlags(&s2, cudaStreamNonBlocking);
        cudaEventCreateWithFlags(&evFork, cudaEventDisableTiming);
        cudaEventCreateWithFlags(&evJoin, cudaEventDisableTiming);
        cudaFuncSetAttribute(proj_f16_kernel,
                             cudaFuncAttributeMaxDynamicSharedMemorySize, 3 * PSTG);
    }

    // fork: adjacency chain on side stream (independent of conv/proj)
    cudaEventRecord(evFork, 0);
    cudaStreamWaitEvent(s2, evFork, 0);
    detect_kernel<<<1, 256, 0, s2>>>((const unsigned int*)ei);
    adj_zero_kernel<<<(NN * (NN / 32) + 255) / 256, 256, 0, s2>>>();
    adj_scatter_kernel<<<(E + 255) / 256, 256, 0, s2>>>(ei, E);
    cudaEventRecord(evJoin, s2);

    // main chain: conv (2 launches) -> proj -> vmean
    convh_kernel<<<(NN * DD / 4 + 255) / 256, 256>>>(x, pxh, pxl, NN * DD / 4);
    dim3 gT(DD / 32, DD / 32, 3);
    dim3 bT(32, 8);
    convTh3_kernel<<<gT, bT>>>(Wq, Wk, Wv);

    dim3 gProj(DD / 128, NN / 128, 3);
    proj_f16_kernel<<<gProj, 256, 3 * PSTG>>>(bq, pq, bk, pk, bv, pv);

    vmean1_kernel<<<64, 256>>>();
    vmean2_kernel<<<1, 256>>>();

    // join adjacency before sparse attention
    cudaStreamWaitEvent(0, evJoin, 0);
    spattn_kernel<<<NN, 256>>>(out);
}

// round 11
// speedup vs baseline: 1.5631x; 1.0091x over previous
#include <cuda_runtime.h>
#include <cuda_fp16.h>
#include <cstddef>
#include <cstdint>

#define NN 8192
#define DD 512
#define SCALE 0.04419417382415922f   // 1/sqrt(512)

// ---------------- scratch (static __device__ — no allocs allowed) ----------
__device__ float g_q[NN * DD];
__device__ float g_k[NN * DD];
__device__ float g_v[NN * DD];
__device__ __half g_vh[NN * DD];                      // fp16 copy of v for PV
__device__ float g_sc_spill[(size_t)NN * NN];         // worst-case scores
__device__ unsigned int g_adj[(size_t)NN * NN / 32];  // 8 MB adjacency bitmask
__device__ float g_vpart[64 * DD];
__device__ float g_vmean[DD];
__device__ int g_is64;
__device__ __half g_xh[NN * DD];
__device__ __half g_xl[NN * DD];
__device__ __half g_wth[3 * DD * DD];
__device__ __half g_wtl[3 * DD * DD];

// ---------------- edge dtype detection -------------------------------------
__global__ void detect_kernel(const unsigned int* __restrict__ w) {
    __shared__ unsigned int red[256];
    unsigned int acc = 0;
    for (int i = threadIdx.x; i < 1024; i += 256) acc |= w[2 * i + 1];
    red[threadIdx.x] = acc;
    __syncthreads();
    #pragma unroll
    for (int s = 128; s > 0; s >>= 1) {
        if (threadIdx.x < s) red[threadIdx.x] |= red[threadIdx.x + s];
        __syncthreads();
    }
    if (threadIdx.x == 0) g_is64 = (red[0] == 0u) ? 1 : 0;
}

// ---------------- adjacency ------------------------------------------------
__global__ void adj_zero_kernel() {
    int i = blockIdx.x * blockDim.x + threadIdx.x;
    if (i < NN * (NN / 32)) g_adj[i] = 0u;
}

__global__ void adj_scatter_kernel(const void* __restrict__ ei, int E) {
    int e = blockIdx.x * blockDim.x + threadIdx.x;
    if (e >= E) return;
    int r, c;
    if (g_is64) {
        const long long* p = (const long long*)ei;
        r = (int)p[e];
        c = (int)p[(size_t)E + e];
    } else {
        const int* p = (const int*)ei;
        r = p[e];
        c = p[(size_t)E + e];
    }
    if ((unsigned)r >= NN || (unsigned)c >= NN) return;
    size_t bit = (size_t)r * NN + (size_t)c;
    atomicOr(&g_adj[bit >> 5], 1u << (bit & 31));
}

// ---------------- helpers ---------------------------------------------------
__device__ __forceinline__ void cp_async16(uint32_t smem_addr, const void* gptr) {
    asm volatile("cp.async.cg.shared.global [%0], [%1], 16;\n"
                 :: "r"(smem_addr), "l"(gptr));
}

__device__ __forceinline__ void ldsm_x4(uint32_t* r, uint32_t addr) {
    asm volatile("ldmatrix.sync.aligned.m8n8.x4.shared.b16 {%0,%1,%2,%3}, [%4];"
                 : "=r"(r[0]), "=r"(r[1]), "=r"(r[2]), "=r"(r[3]) : "r"(addr));
}

__device__ __forceinline__ void mma_f16(float* d, const uint32_t* a, uint32_t b0, uint32_t b1) {
    asm volatile(
        "mma.sync.aligned.m16n8k16.row.col.f32.f16.f16.f32 "
        "{%0,%1,%2,%3}, {%4,%5,%6,%7}, {%8,%9}, {%0,%1,%2,%3};\n"
        : "+f"(d[0]), "+f"(d[1]), "+f"(d[2]), "+f"(d[3])
        : "r"(a[0]), "r"(a[1]), "r"(a[2]), "r"(a[3]), "r"(b0), "r"(b1));
}

#define SWZ(row, chunk) ((((chunk) ^ (((row) >> 1) & 3)) << 4))

// ---------------- fp16 hi/lo precompute -------------------------------------
__global__ void convh_kernel(const float* __restrict__ src,
                             __half* __restrict__ hi,
                             __half* __restrict__ lo, int n4) {
    int i = blockIdx.x * 256 + threadIdx.x;
    if (i >= n4) return;
    float4 v = ((const float4*)src)[i];
    __half h0 = __float2half_rn(v.x), h1 = __float2half_rn(v.y);
    __half h2 = __float2half_rn(v.z), h3 = __float2half_rn(v.w);
    __half l0 = __float2half_rn(v.x - __half2float(h0));
    __half l1 = __float2half_rn(v.y - __half2float(h1));
    __half l2 = __float2half_rn(v.z - __half2float(h2));
    __half l3 = __float2half_rn(v.w - __half2float(h3));
    __half2 hp[2] = {__halves2half2(h0, h1), __halves2half2(h2, h3)};
    __half2 lp[2] = {__halves2half2(l0, l1), __halves2half2(l2, l3)};
    ((float2*)hi)[i] = *(float2*)hp;
    ((float2*)lo)[i] = *(float2*)lp;
}

// fused: W transpose + fp16 hi/lo split for all 3 weights
__global__ void convTh3_kernel(const float* __restrict__ Wq,
                               const float* __restrict__ Wk,
                               const float* __restrict__ Wv) {
    const int z = blockIdx.z;
    const float* W = (z == 0) ? Wq : (z == 1) ? Wk : Wv;
    __half* hi = g_wth + (size_t)z * DD * DD;
    __half* lo = g_wtl + (size_t)z * DD * DD;

    __shared__ float tile[32][33];
    const int k0 = blockIdx.x * 32, n0 = blockIdx.y * 32;
    const int tx = threadIdx.x, ty = threadIdx.y;
    #pragma unroll
    for (int r = 0; r < 32; r += 8)
        tile[ty + r][tx] = W[(size_t)(k0 + ty + r) * DD + n0 + tx];
    __syncthreads();
    #pragma unroll
    for (int r = 0; r < 32; r += 8) {
        float v = tile[tx][ty + r];
        __half h = __float2half_rn(v);
        hi[(size_t)(n0 + ty + r) * DD + k0 + tx] = h;
        lo[(size_t)(n0 + ty + r) * DD + k0 + tx] = __float2half_rn(v - __half2float(h));
    }
}

// ---------------- QKV projection: fp16 mma.sync + ldmatrix, 3-stage ring ----
#define PSTG 32768

__global__ void __launch_bounds__(256, 2)
proj_f16_kernel(const float* __restrict__ bq, float* __restrict__ oq,
                const float* __restrict__ bk, float* __restrict__ ok,
                const float* __restrict__ bv, float* __restrict__ ov)
{
    extern __shared__ char dsm[];
    const uint32_t sbase = (uint32_t)__cvta_generic_to_shared(dsm);

    const int z = blockIdx.z;
    const float* bias = (z == 0) ? bq : (z == 1) ? bk : bv;
    float* C          = (z == 0) ? oq : (z == 1) ? ok : ov;

    const int t = threadIdx.x;
    const int lane = t & 31;
    const int wid  = t >> 5;
    const int warpRow = wid >> 1;
    const int warpCol = wid & 1;
    const int g  = lane >> 2;
    const int tg = lane & 3;
    const int bm = blockIdx.y;
    const int bn = blockIdx.x;

    const int lrow = t >> 1;
    const int lc0  = (t & 1) * 2;
    const __half* pAh = g_xh + (size_t)(bm * 128 + lrow) * DD;
    const __half* pAl = g_xl + (size_t)(bm * 128 + lrow) * DD;
    const __half* pBh = g_wth + (size_t)z * DD * DD + (size_t)(bn * 128 + lrow) * DD;
    const __half* pBl = g_wtl + (size_t)z * DD * DD + (size_t)(bn * 128 + lrow) * DD;

    const int rsel = (lane & 7) + ((lane >> 3) & 1) * 8;
    const int ksel = (lane >> 4) & 1;

    float d[2][8][4];
    #pragma unroll
    for (int mt = 0; mt < 2; mt++)
        #pragma unroll
        for (int nt = 0; nt < 8; nt++)
            #pragma unroll
            for (int r = 0; r < 4; r++) d[mt][nt][r] = 0.0f;

    #define LOADSTAGE(s, buf) do {                                            \
        const int _kh = (s) * 32;                                             \
        const uint32_t _sb = sbase + (buf) * PSTG;                            \
        _Pragma("unroll")                                                     \
        for (int _cc = 0; _cc < 2; _cc++) {                                   \
            const int _c = lc0 + _cc;                                         \
            const uint32_t _dst = lrow * 64 + SWZ(lrow, _c);                  \
            cp_async16(_sb + _dst,         pAh + _kh + _c * 8);               \
            cp_async16(_sb + 8192 + _dst,  pAl + _kh + _c * 8);               \
            cp_async16(_sb + 16384 + _dst, pBh + _kh + _c * 8);               \
            cp_async16(_sb + 24576 + _dst, pBl + _kh + _c * 8);               \
        }                                                                     \
        asm volatile("cp.async.commit_group;\n");                             \
    } while (0)

    LOADSTAGE(0, 0);
    LOADSTAGE(1, 1);

    const int NST = DD / 32;
    int buf = 0;
    for (int s = 0; s < NST; s++) {
        if (s < NST - 1) asm volatile("cp.async.wait_group 1;\n" ::: "memory");
        else             asm volatile("cp.async.wait_group 0;\n" ::: "memory");
        __syncthreads();

        if (s + 2 < NST) {
            int nb = buf + 2; if (nb >= 3) nb -= 3;
            LOADSTAGE(s + 2, nb);
        }

        const uint32_t sb = sbase + buf * PSTG;

        #pragma unroll
        for (int ks = 0; ks < 2; ks++) {
            const int chunk = ks * 2 + ksel;
            uint32_t ah[2][4], al[2][4];
            #pragma unroll
            for (int mt = 0; mt < 2; mt++) {
                const int rm = warpRow * 32 + mt * 16 + rsel;
                const uint32_t ao = sb + rm * 64 + SWZ(rm, chunk);
                ldsm_x4(ah[mt], ao);
                ldsm_x4(al[mt], ao + 8192);
            }
            #pragma unroll
            for (int half = 0; half < 2; half++) {
                uint32_t bh[2][4], bl[2][4];
                #pragma unroll
                for (int p = 0; p < 2; p++) {
                    const int rn = warpCol * 64 + (half * 2 + p) * 16 + rsel;
                    const uint32_t bo = sb + 16384 + rn * 64 + SWZ(rn, chunk);
                    ldsm_x4(bh[p], bo);
                    ldsm_x4(bl[p], bo + 8192);
                }
                #pragma unroll
                for (int p = 0; p < 2; p++)
                    #pragma unroll
                    for (int sub = 0; sub < 2; sub++)
                        #pragma unroll
                        for (int mt = 0; mt < 2; mt++)
                            mma_f16(d[mt][half * 4 + p * 2 + sub], ah[mt],
                                    bh[p][sub], bh[p][sub + 2]);
                #pragma unroll
                for (int p = 0; p < 2; p++)
                    #pragma unroll
                    for (int sub = 0; sub < 2; sub++)
                        #pragma unroll
                        for (int mt = 0; mt < 2; mt++)
                            mma_f16(d[mt][half * 4 + p * 2 + sub], ah[mt],
                                    bl[p][sub], bl[p][sub + 2]);
                #pragma unroll
                for (int p = 0; p < 2; p++)
                    #pragma unroll
                    for (int sub = 0; sub < 2; sub++)
                        #pragma unroll
                        for (int mt = 0; mt < 2; mt++)
                            mma_f16(d[mt][half * 4 + p * 2 + sub], al[mt],
                                    bh[p][sub], bh[p][sub + 2]);
            }
        }
        buf++; if (buf == 3) buf = 0;
    }

    #pragma unroll
    for (int mt = 0; mt < 2; mt++) {
        const int row = bm * 128 + warpRow * 32 + mt * 16 + g;
        #pragma unroll
        for (int nt = 0; nt < 8; nt++) {
            const int col = bn * 128 + warpCol * 64 + nt * 8 + 2 * tg;
            float2 bb = *(const float2*)&bias[col];
            float2 lo = {d[mt][nt][0] + bb.x, d[mt][nt][1] + bb.y};
            float2 hi = {d[mt][nt][2] + bb.x, d[mt][nt][3] + bb.y};
            *(float2*)&C[(size_t)row * DD + col]       = lo;
            *(float2*)&C[(size_t)(row + 8) * DD + col] = hi;
            if (z == 2) {   // fp16 copy of v for the PV pass
                *(__half2*)&g_vh[(size_t)row * DD + col] =
                    __floats2half2_rn(lo.x, lo.y);
                *(__half2*)&g_vh[(size_t)(row + 8) * DD + col] =
                    __floats2half2_rn(hi.x, hi.y);
            }
        }
    }
}

// ---------------- v column mean (degree-0 rows), deterministic 2-stage -----
__global__ void vmean1_kernel() {
    const int b = blockIdx.x;
    const int t = threadIdx.x;
    float s0 = 0.f, s1 = 0.f;
    for (int r = 0; r < 128; r++) {
        const float* v = &g_v[(size_t)(b * 128 + r) * DD];
        s0 += v[t];
        s1 += v[t + 256];
    }
    g_vpart[b * DD + t] = s0;
    g_vpart[b * DD + t + 256] = s1;
}

__global__ void vmean2_kernel() {
    const int t = threadIdx.x;
    float s0 = 0.f, s1 = 0.f;
    for (int b = 0; b < 64; b++) {
        s0 += g_vpart[b * DD + t];
        s1 += g_vpart[b * DD + t + 256];
    }
    g_vmean[t]       = s0 * (1.0f / NN);
    g_vmean[t + 256] = s1 * (1.0f / NN);
}

// ---------------- sparse attention: one block (256 thr) per row -----------
#define SC_CAP 1024

__global__ __launch_bounds__(256)
void spattn_kernel(float* __restrict__ out)
{
    const int i = blockIdx.x;
    const int t = threadIdx.x;
    const int lane = t & 31;
    const int wid  = t >> 5;

    __shared__ __align__(16) float qs[DD];
    __shared__ int   nbr[SC_CAP];
    __shared__ float sc[SC_CAP];
    __shared__ int   scan[256];
    __shared__ float red[256];

    for (int d = t; d < DD; d += 256) qs[d] = g_q[(size_t)i * DD + d];

    unsigned word = g_adj[i * 256 + t];
    int pc = __popc(word);
    scan[t] = pc;
    __syncthreads();
    #pragma unroll
    for (int off = 1; off < 256; off <<= 1) {
        int mine = scan[t];
        int add  = (t >= off) ? scan[t - off] : 0;
        __syncthreads();
        scan[t] = mine + add;
        __syncthreads();
    }
    const int deg = scan[255];

    if (deg == 0) {
        for (int d = t; d < DD; d += 256)
            out[(size_t)i * DD + d] = g_vmean[d];
        return;
    }

    if (deg <= SC_CAP) {
        {
            int base = scan[t] - pc;
            unsigned w = word;
            while (w) {
                int b = __ffs(w) - 1;
                w &= w - 1;
                nbr[base++] = t * 32 + b;
            }
        }
        __syncthreads();

        // SDDMM: warp per neighbor, float4 loads
        for (int s = wid; s < deg; s += 8) {
            const float4* kj = (const float4*)&g_k[(size_t)nbr[s] * DD];
            const float4* q4 = (const float4*)qs;
            float acc = 0.f;
            #pragma unroll
            for (int d4 = lane; d4 < DD / 4; d4 += 32) {
                float4 kv = kj[d4];
                float4 qv = q4[d4];
                acc += qv.x * kv.x + qv.y * kv.y + qv.z * kv.z + qv.w * kv.w;
            }
            #pragma unroll
            for (int o = 16; o > 0; o >>= 1) acc += __shfl_xor_sync(0xffffffffu, acc, o);
            if (lane == 0) sc[s] = acc * SCALE;
        }
        __syncthreads();

        float m = -3.4e38f;
        for (int s = t; s < deg; s += 256) m = fmaxf(m, sc[s]);
        red[t] = m;
        __syncthreads();
        #pragma unroll
        for (int s = 128; s > 0; s >>= 1) {
            if (t < s) red[t] = fmaxf(red[t], red[t + s]);
            __syncthreads();
        }
        m = red[0];
        __syncthreads();

        float sum = 0.f;
        for (int s = t; s < deg; s += 256) {
            float p = __expf(sc[s] - m);
            sc[s] = p;
            sum += p;
        }
        red[t] = sum;
        __syncthreads();
        #pragma unroll
        for (int s = 128; s > 0; s >>= 1) {
            if (t < s) red[t] += red[t + s];
            __syncthreads();
        }
        const float inv = 1.0f / red[0];
        __syncthreads();

        // PV: thread owns dims 2t, 2t+1; fp16 v, __half2 loads
        float o0 = 0.f, o1 = 0.f;
        int s = 0;
        for (; s + 1 < deg; s += 2) {
            float p0 = sc[s], p1 = sc[s + 1];
            __half2 v0 = *(const __half2*)&g_vh[(size_t)nbr[s] * DD + 2 * t];
            __half2 v1 = *(const __half2*)&g_vh[(size_t)nbr[s + 1] * DD + 2 * t];
            float2 f0 = __half22float2(v0);
            float2 f1 = __half22float2(v1);
            o0 += p0 * f0.x + p1 * f1.x;
            o1 += p0 * f0.y + p1 * f1.y;
        }
        if (s < deg) {
            float p = sc[s];
            float2 f = __half22float2(*(const __half2*)&g_vh[(size_t)nbr[s] * DD + 2 * t]);
            o0 += p * f.x;
            o1 += p * f.y;
        }
        float2 o = {o0 * inv, o1 * inv};
        *(float2*)&out[(size_t)i * DD + 2 * t] = o;
    } else {
        float* scores = &g_sc_spill[(size_t)i * NN];
        for (int c = wid; c < NN; c += 8) {
            bool edge = (g_adj[i * 256 + (c >> 5)] >> (c & 31)) & 1u;
            float acc = 0.f;
            if (edge) {
                const float* kj = &g_k[(size_t)c * DD];
                for (int d = lane; d < DD; d += 32) acc += qs[d] * kj[d];
                #pragma unroll
                for (int o = 16; o > 0; o >>= 1) acc += __shfl_xor_sync(0xffffffffu, acc, o);
            }
            if (lane == 0) scores[c] = edge ? acc * SCALE : -3.4e38f;
        }
        __syncthreads();

        float m = -3.4e38f;
        for (int c = t; c < NN; c += 256) m = fmaxf(m, scores[c]);
        red[t] = m;
        __syncthreads();
        #pragma unroll
        for (int s = 128; s > 0; s >>= 1) {
            if (t < s) red[t] = fmaxf(red[t], red[t + s]);
            __syncthreads();
        }
        m = red[0];
        __syncthreads();

        float sum = 0.f;
        for (int c = t; c < NN; c += 256) {
            float p = __expf(scores[c] - m);
            scores[c] = p;
            sum += p;
        }
        red[t] = sum;
        __syncthreads();
        #pragma unroll
        for (int s = 128; s > 0; s >>= 1) {
            if (t < s) red[t] += red[t + s];
            __syncthreads();
        }
        const float inv = 1.0f / red[0];
        __syncthreads();

        float o0 = 0.f, o1 = 0.f;
        for (int c = 0; c < NN; c++) {
            float p = scores[c];
            if (p != 0.f) {
                const float* vj = &g_v[(size_t)c * DD];
                o0 += p * vj[t];
                o1 += p * vj[t + 256];
            }
        }
        out[(size_t)i * DD + t]       = o0 * inv;
        out[(size_t)i * DD + t + 256] = o1 * inv;
    }
}

// ---------------- launch ---------------------------------------------------
extern "C" void kernel_launch(void* const* d_in, const int* in_sizes, int n_in,
                              void* d_out, int out_size)
{
    const float* x  = (const float*)d_in[0];
    const void*  ei = d_in[1];
    const float* Wq = (const float*)d_in[2];
    const float* bq = (const float*)d_in[3];
    const float* Wk = (const float*)d_in[4];
    const float* bk = (const float*)d_in[5];
    const float* Wv = (const float*)d_in[6];
    const float* bv = (const float*)d_in[7];
    float* out = (float*)d_out;
    const int E = in_sizes[1] / 2;

    float *pq, *pk, *pv;
    __half *pxh, *pxl;
    cudaGetSymbolAddress((void**)&pq, g_q);
    cudaGetSymbolAddress((void**)&pk, g_k);
    cudaGetSymbolAddress((void**)&pv, g_v);
    cudaGetSymbolAddress((void**)&pxh, g_xh);
    cudaGetSymbolAddress((void**)&pxl, g_xl);

    static cudaStream_t s2 = nullptr;
    static cudaEvent_t evFork = nullptr, evJoin = nullptr;
    if (!s2) {
        cudaStreamCreateWithFlags(&s2, cudaStreamNonBlocking);
        cudaEventCreateWithFlags(&evFork, cudaEventDisableTiming);
        cudaEventCreateWithFlags(&evJoin, cudaEventDisableTiming);
        cudaFuncSetAttribute(proj_f16_kernel,
                             cudaFuncAttributeMaxDynamicSharedMemorySize, 3 * PSTG);
    }

    // fork: adjacency chain on side stream
    cudaEventRecord(evFork, 0);
    cudaStreamWaitEvent(s2, evFork, 0);
    detect_kernel<<<1, 256, 0, s2>>>((const unsigned int*)ei);
    adj_zero_kernel<<<(NN * (NN / 32) + 255) / 256, 256, 0, s2>>>();
    adj_scatter_kernel<<<(E + 255) / 256, 256, 0, s2>>>(ei, E);
    cudaEventRecord(evJoin, s2);

    // main chain
    convh_kernel<<<(NN * DD / 4 + 255) / 256, 256>>>(x, pxh, pxl, NN * DD / 4);
    dim3 gT(DD / 32, DD / 32, 3);
    dim3 bT(32, 8);
    convTh3_kernel<<<gT, bT>>>(Wq, Wk, Wv);

    dim3 gProj(DD / 128, NN / 128, 3);
    proj_f16_kernel<<<gProj, 256, 3 * PSTG>>>(bq, pq, bk, pk, bv, pv);

    vmean1_kernel<<<64, 256>>>();
    vmean2_kernel<<<1, 256>>>();

    cudaStreamWaitEvent(0, evJoin, 0);
    spattn_kernel<<<NN, 256>>>(out);
}

// round 12
// speedup vs baseline: 1.5710x; 1.0051x over previous
#include <cuda_runtime.h>
#include <cuda_fp16.h>
#include <cstddef>
#include <cstdint>

#define NN 8192
#define DD 512
#define SCALE 0.04419417382415922f   // 1/sqrt(512)

// ---------------- scratch (static __device__ — no allocs allowed) ----------
__device__ float g_q[NN * DD];
__device__ float g_k[NN * DD];
__device__ float g_v[NN * DD];
__device__ __half g_vh[NN * DD];                      // fp16 copy of v for PV
__device__ float g_sc_spill[(size_t)NN * NN];         // worst-case scores
__device__ unsigned int g_adj[(size_t)NN * NN / 32];  // 8 MB adjacency bitmask
__device__ float g_vpart[64 * DD];
__device__ float g_vmean[DD];
__device__ int g_is64;
__device__ __half g_xh[NN * DD];
__device__ __half g_xl[NN * DD];
__device__ __half g_wth[3 * DD * DD];
__device__ __half g_wtl[3 * DD * DD];

// ---------------- no-op (ncu launch-slot alignment) -------------------------
__global__ void noop_kernel() {}

// ---------------- edge dtype detection -------------------------------------
__global__ void detect_kernel(const unsigned int* __restrict__ w) {
    __shared__ unsigned int red[256];
    unsigned int acc = 0;
    for (int i = threadIdx.x; i < 1024; i += 256) acc |= w[2 * i + 1];
    red[threadIdx.x] = acc;
    __syncthreads();
    #pragma unroll
    for (int s = 128; s > 0; s >>= 1) {
        if (threadIdx.x < s) red[threadIdx.x] |= red[threadIdx.x + s];
        __syncthreads();
    }
    if (threadIdx.x == 0) g_is64 = (red[0] == 0u) ? 1 : 0;
}

// ---------------- adjacency ------------------------------------------------
__global__ void adj_zero_kernel() {
    int i = blockIdx.x * blockDim.x + threadIdx.x;
    if (i < NN * (NN / 32)) g_adj[i] = 0u;
}

__global__ void adj_scatter_kernel(const void* __restrict__ ei, int E) {
    int e = blockIdx.x * blockDim.x + threadIdx.x;
    if (e >= E) return;
    int r, c;
    if (g_is64) {
        const long long* p = (const long long*)ei;
        r = (int)p[e];
        c = (int)p[(size_t)E + e];
    } else {
        const int* p = (const int*)ei;
        r = p[e];
        c = p[(size_t)E + e];
    }
    if ((unsigned)r >= NN || (unsigned)c >= NN) return;
    size_t bit = (size_t)r * NN + (size_t)c;
    atomicOr(&g_adj[bit >> 5], 1u << (bit & 31));
}

// ---------------- helpers ---------------------------------------------------
__device__ __forceinline__ void cp_async16(uint32_t smem_addr, const void* gptr) {
    asm volatile("cp.async.cg.shared.global [%0], [%1], 16;\n"
                 :: "r"(smem_addr), "l"(gptr));
}

__device__ __forceinline__ void ldsm_x4(uint32_t* r, uint32_t addr) {
    asm volatile("ldmatrix.sync.aligned.m8n8.x4.shared.b16 {%0,%1,%2,%3}, [%4];"
                 : "=r"(r[0]), "=r"(r[1]), "=r"(r[2]), "=r"(r[3]) : "r"(addr));
}

__device__ __forceinline__ void mma_f16(float* d, const uint32_t* a, uint32_t b0, uint32_t b1) {
    asm volatile(
        "mma.sync.aligned.m16n8k16.row.col.f32.f16.f16.f32 "
        "{%0,%1,%2,%3}, {%4,%5,%6,%7}, {%8,%9}, {%0,%1,%2,%3};\n"
        : "+f"(d[0]), "+f"(d[1]), "+f"(d[2]), "+f"(d[3])
        : "r"(a[0]), "r"(a[1]), "r"(a[2]), "r"(a[3]), "r"(b0), "r"(b1));
}

#define SWZ(row, chunk) ((((chunk) ^ (((row) >> 1) & 3)) << 4))

// ---------------- fp16 hi/lo precompute -------------------------------------
__global__ void convh_kernel(const float* __restrict__ src,
                             __half* __restrict__ hi,
                             __half* __restrict__ lo, int n4) {
    int i = blockIdx.x * 256 + threadIdx.x;
    if (i >= n4) return;
    float4 v = ((const float4*)src)[i];
    __half h0 = __float2half_rn(v.x), h1 = __float2half_rn(v.y);
    __half h2 = __float2half_rn(v.z), h3 = __float2half_rn(v.w);
    __half l0 = __float2half_rn(v.x - __half2float(h0));
    __half l1 = __float2half_rn(v.y - __half2float(h1));
    __half l2 = __float2half_rn(v.z - __half2float(h2));
    __half l3 = __float2half_rn(v.w - __half2float(h3));
    __half2 hp[2] = {__halves2half2(h0, h1), __halves2half2(h2, h3)};
    __half2 lp[2] = {__halves2half2(l0, l1), __halves2half2(l2, l3)};
    ((float2*)hi)[i] = *(float2*)hp;
    ((float2*)lo)[i] = *(float2*)lp;
}

// fused: W transpose + fp16 hi/lo split for all 3 weights
__global__ void convTh3_kernel(const float* __restrict__ Wq,
                               const float* __restrict__ Wk,
                               const float* __restrict__ Wv) {
    const int z = blockIdx.z;
    const float* W = (z == 0) ? Wq : (z == 1) ? Wk : Wv;
    __half* hi = g_wth + (size_t)z * DD * DD;
    __half* lo = g_wtl + (size_t)z * DD * DD;

    __shared__ float tile[32][33];
    const int k0 = blockIdx.x * 32, n0 = blockIdx.y * 32;
    const int tx = threadIdx.x, ty = threadIdx.y;
    #pragma unroll
    for (int r = 0; r < 32; r += 8)
        tile[ty + r][tx] = W[(size_t)(k0 + ty + r) * DD + n0 + tx];
    __syncthreads();
    #pragma unroll
    for (int r = 0; r < 32; r += 8) {
        float v = tile[tx][ty + r];
        __half h = __float2half_rn(v);
        hi[(size_t)(n0 + ty + r) * DD + k0 + tx] = h;
        lo[(size_t)(n0 + ty + r) * DD + k0 + tx] = __float2half_rn(v - __half2float(h));
    }
}

// ---------------- QKV projection: fp16 mma.sync + ldmatrix, 3-stage ring ----
#define PSTG 32768

__global__ void __launch_bounds__(256, 2)
proj_f16_kernel(const float* __restrict__ bq, float* __restrict__ oq,
                const float* __restrict__ bk, float* __restrict__ ok,
                const float* __restrict__ bv, float* __restrict__ ov)
{
    extern __shared__ char dsm[];
    const uint32_t sbase = (uint32_t)__cvta_generic_to_shared(dsm);

    const int z = blockIdx.z;
    const float* bias = (z == 0) ? bq : (z == 1) ? bk : bv;
    float* C          = (z == 0) ? oq : (z == 1) ? ok : ov;

    const int t = threadIdx.x;
    const int lane = t & 31;
    const int wid  = t >> 5;
    const int warpRow = wid >> 1;
    const int warpCol = wid & 1;
    const int g  = lane >> 2;
    const int tg = lane & 3;
    const int bm = blockIdx.y;
    const int bn = blockIdx.x;

    const int lrow = t >> 1;
    const int lc0  = (t & 1) * 2;
    const __half* pAh = g_xh + (size_t)(bm * 128 + lrow) * DD;
    const __half* pAl = g_xl + (size_t)(bm * 128 + lrow) * DD;
    const __half* pBh = g_wth + (size_t)z * DD * DD + (size_t)(bn * 128 + lrow) * DD;
    const __half* pBl = g_wtl + (size_t)z * DD * DD + (size_t)(bn * 128 + lrow) * DD;

    const int rsel = (lane & 7) + ((lane >> 3) & 1) * 8;
    const int ksel = (lane >> 4) & 1;

    float d[2][8][4];
    #pragma unroll
    for (int mt = 0; mt < 2; mt++)
        #pragma unroll
        for (int nt = 0; nt < 8; nt++)
            #pragma unroll
            for (int r = 0; r < 4; r++) d[mt][nt][r] = 0.0f;

    #define LOADSTAGE(s, buf) do {                                            \
        const int _kh = (s) * 32;                                             \
        const uint32_t _sb = sbase + (buf) * PSTG;                            \
        _Pragma("unroll")                                                     \
        for (int _cc = 0; _cc < 2; _cc++) {                                   \
            const int _c = lc0 + _cc;                                         \
            const uint32_t _dst = lrow * 64 + SWZ(lrow, _c);                  \
            cp_async16(_sb + _dst,         pAh + _kh + _c * 8);               \
            cp_async16(_sb + 8192 + _dst,  pAl + _kh + _c * 8);               \
            cp_async16(_sb + 16384 + _dst, pBh + _kh + _c * 8);               \
            cp_async16(_sb + 24576 + _dst, pBl + _kh + _c * 8);               \
        }                                                                     \
        asm volatile("cp.async.commit_group;\n");                             \
    } while (0)

    LOADSTAGE(0, 0);
    LOADSTAGE(1, 1);

    const int NST = DD / 32;
    int buf = 0;
    for (int s = 0; s < NST; s++) {
        if (s < NST - 1) asm volatile("cp.async.wait_group 1;\n" ::: "memory");
        else             asm volatile("cp.async.wait_group 0;\n" ::: "memory");
        __syncthreads();

        if (s + 2 < NST) {
            int nb = buf + 2; if (nb >= 3) nb -= 3;
            LOADSTAGE(s + 2, nb);
        }

        const uint32_t sb = sbase + buf * PSTG;

        #pragma unroll
        for (int ks = 0; ks < 2; ks++) {
            const int chunk = ks * 2 + ksel;
            uint32_t ah[2][4], al[2][4];
            #pragma unroll
            for (int mt = 0; mt < 2; mt++) {
                const int rm = warpRow * 32 + mt * 16 + rsel;
                const uint32_t ao = sb + rm * 64 + SWZ(rm, chunk);
                ldsm_x4(ah[mt], ao);
                ldsm_x4(al[mt], ao + 8192);
            }
            #pragma unroll
            for (int half = 0; half < 2; half++) {
                uint32_t bh[2][4], bl[2][4];
                #pragma unroll
                for (int p = 0; p < 2; p++) {
                    const int rn = warpCol * 64 + (half * 2 + p) * 16 + rsel;
                    const uint32_t bo = sb + 16384 + rn * 64 + SWZ(rn, chunk);
                    ldsm_x4(bh[p], bo);
                    ldsm_x4(bl[p], bo + 8192);
                }
                #pragma unroll
                for (int p = 0; p < 2; p++)
                    #pragma unroll
                    for (int sub = 0; sub < 2; sub++)
                        #pragma unroll
                        for (int mt = 0; mt < 2; mt++)
                            mma_f16(d[mt][half * 4 + p * 2 + sub], ah[mt],
                                    bh[p][sub], bh[p][sub + 2]);
                #pragma unroll
                for (int p = 0; p < 2; p++)
                    #pragma unroll
                    for (int sub = 0; sub < 2; sub++)
                        #pragma unroll
                        for (int mt = 0; mt < 2; mt++)
                            mma_f16(d[mt][half * 4 + p * 2 + sub], ah[mt],
                                    bl[p][sub], bl[p][sub + 2]);
                #pragma unroll
                for (int p = 0; p < 2; p++)
                    #pragma unroll
                    for (int sub = 0; sub < 2; sub++)
                        #pragma unroll
                        for (int mt = 0; mt < 2; mt++)
                            mma_f16(d[mt][half * 4 + p * 2 + sub], al[mt],
                                    bh[p][sub], bh[p][sub + 2]);
            }
        }
        buf++; if (buf == 3) buf = 0;
    }

    #pragma unroll
    for (int mt = 0; mt < 2; mt++) {
        const int row = bm * 128 + warpRow * 32 + mt * 16 + g;
        #pragma unroll
        for (int nt = 0; nt < 8; nt++) {
            const int col = bn * 128 + warpCol * 64 + nt * 8 + 2 * tg;
            float2 bb = *(const float2*)&bias[col];
            float2 lo = {d[mt][nt][0] + bb.x, d[mt][nt][1] + bb.y};
            float2 hi = {d[mt][nt][2] + bb.x, d[mt][nt][3] + bb.y};
            *(float2*)&C[(size_t)row * DD + col]       = lo;
            *(float2*)&C[(size_t)(row + 8) * DD + col] = hi;
            if (z == 2) {
                *(__half2*)&g_vh[(size_t)row * DD + col] =
                    __floats2half2_rn(lo.x, lo.y);
                *(__half2*)&g_vh[(size_t)(row + 8) * DD + col] =
                    __floats2half2_rn(hi.x, hi.y);
            }
        }
    }
}

// ---------------- v column mean (degree-0 rows), deterministic 2-stage -----
__global__ void vmean1_kernel() {
    const int b = blockIdx.x;
    const int t = threadIdx.x;
    float s0 = 0.f, s1 = 0.f;
    for (int r = 0; r < 128; r++) {
        const float* v = &g_v[(size_t)(b * 128 + r) * DD];
        s0 += v[t];
        s1 += v[t + 256];
    }
    g_vpart[b * DD + t] = s0;
    g_vpart[b * DD + t + 256] = s1;
}

__global__ void vmean2_kernel() {
    const int t = threadIdx.x;
    float s0 = 0.f, s1 = 0.f;
    for (int b = 0; b < 64; b++) {
        s0 += g_vpart[b * DD + t];
        s1 += g_vpart[b * DD + t + 256];
    }
    g_vmean[t]       = s0 * (1.0f / NN);
    g_vmean[t + 256] = s1 * (1.0f / NN);
}

// ---------------- sparse attention: one block (256 thr) per row -----------
#define SC_CAP 1024

__global__ __launch_bounds__(256)
void spattn_kernel(float* __restrict__ out)
{
    const int i = blockIdx.x;
    const int t = threadIdx.x;
    const int lane = t & 31;
    const int wid  = t >> 5;

    __shared__ __align__(16) float qs[DD];
    __shared__ int   nbr[SC_CAP];
    __shared__ float sc[SC_CAP];
    __shared__ int   scan[256];
    __shared__ float red[256];

    for (int d = t; d < DD; d += 256) qs[d] = g_q[(size_t)i * DD + d];

    unsigned word = g_adj[i * 256 + t];
    int pc = __popc(word);
    scan[t] = pc;
    __syncthreads();
    #pragma unroll
    for (int off = 1; off < 256; off <<= 1) {
        int mine = scan[t];
        int add  = (t >= off) ? scan[t - off] : 0;
        __syncthreads();
        scan[t] = mine + add;
        __syncthreads();
    }
    const int deg = scan[255];

    if (deg == 0) {
        for (int d = t; d < DD; d += 256)
            out[(size_t)i * DD + d] = g_vmean[d];
        return;
    }

    if (deg <= SC_CAP) {
        {
            int base = scan[t] - pc;
            unsigned w = word;
            while (w) {
                int b = __ffs(w) - 1;
                w &= w - 1;
                nbr[base++] = t * 32 + b;
            }
        }
        __syncthreads();

        // SDDMM: 2 concurrent dots per warp (MLP x2)
        for (int s = wid * 2; s < deg; s += 16) {
            const bool has2 = (s + 1 < deg);
            const float4* k0 = (const float4*)&g_k[(size_t)nbr[s] * DD];
            const float4* k1 = (const float4*)&g_k[(size_t)nbr[has2 ? s + 1 : s] * DD];
            const float4* q4 = (const float4*)qs;
            float acc0 = 0.f, acc1 = 0.f;
            #pragma unroll
            for (int d4 = lane; d4 < DD / 4; d4 += 32) {
                float4 qv  = q4[d4];
                float4 kv0 = k0[d4];
                float4 kv1 = k1[d4];
                acc0 += qv.x * kv0.x + qv.y * kv0.y + qv.z * kv0.z + qv.w * kv0.w;
                acc1 += qv.x * kv1.x + qv.y * kv1.y + qv.z * kv1.z + qv.w * kv1.w;
            }
            #pragma unroll
            for (int o = 16; o > 0; o >>= 1) {
                acc0 += __shfl_xor_sync(0xffffffffu, acc0, o);
                acc1 += __shfl_xor_sync(0xffffffffu, acc1, o);
            }
            if (lane == 0) {
                sc[s] = acc0 * SCALE;
                if (has2) sc[s + 1] = acc1 * SCALE;
            }
        }
        __syncthreads();

        float m = -3.4e38f;
        for (int s = t; s < deg; s += 256) m = fmaxf(m, sc[s]);
        red[t] = m;
        __syncthreads();
        #pragma unroll
        for (int s = 128; s > 0; s >>= 1) {
            if (t < s) red[t] = fmaxf(red[t], red[t + s]);
            __syncthreads();
        }
        m = red[0];
        __syncthreads();

        float sum = 0.f;
        for (int s = t; s < deg; s += 256) {
            float p = __expf(sc[s] - m);
            sc[s] = p;
            sum += p;
        }
        red[t] = sum;
        __syncthreads();
        #pragma unroll
        for (int s = 128; s > 0; s >>= 1) {
            if (t < s) red[t] += red[t + s];
            __syncthreads();
        }
        const float inv = 1.0f / red[0];
        __syncthreads();

        // PV: unroll 4, loads issued before FMA chain (MLP 4)
        float o0 = 0.f, o1 = 0.f;
        int s = 0;
        for (; s + 3 < deg; s += 4) {
            __half2 v0 = *(const __half2*)&g_vh[(size_t)nbr[s]     * DD + 2 * t];
            __half2 v1 = *(const __half2*)&g_vh[(size_t)nbr[s + 1] * DD + 2 * t];
            __half2 v2 = *(const __half2*)&g_vh[(size_t)nbr[s + 2] * DD + 2 * t];
            __half2 v3 = *(const __half2*)&g_vh[(size_t)nbr[s + 3] * DD + 2 * t];
            float p0 = sc[s], p1 = sc[s + 1], p2 = sc[s + 2], p3 = sc[s + 3];
            float2 f0 = __half22float2(v0);
            float2 f1 = __half22float2(v1);
            float2 f2 = __half22float2(v2);
            float2 f3 = __half22float2(v3);
            o0 += p0 * f0.x + p1 * f1.x + p2 * f2.x + p3 * f3.x;
            o1 += p0 * f0.y + p1 * f1.y + p2 * f2.y + p3 * f3.y;
        }
        for (; s < deg; s++) {
            float p = sc[s];
            float2 f = __half22float2(*(const __half2*)&g_vh[(size_t)nbr[s] * DD + 2 * t]);
            o0 += p * f.x;
            o1 += p * f.y;
        }
        float2 o = {o0 * inv, o1 * inv};
        *(float2*)&out[(size_t)i * DD + 2 * t] = o;
    } else {
        float* scores = &g_sc_spill[(size_t)i * NN];
        for (int c = wid; c < NN; c += 8) {
            bool edge = (g_adj[i * 256 + (c >> 5)] >> (c & 31)) & 1u;
            float acc = 0.f;
            if (edge) {
                const float* kj = &g_k[(size_t)c * DD];
                for (int d = lane; d < DD; d += 32) acc += qs[d] * kj[d];
                #pragma unroll
                for (int o = 16; o > 0; o >>= 1) acc += __shfl_xor_sync(0xffffffffu, acc, o);
            }
            if (lane == 0) scores[c] = edge ? acc * SCALE : -3.4e38f;
        }
        __syncthreads();

        float m = -3.4e38f;
        for (int c = t; c < NN; c += 256) m = fmaxf(m, scores[c]);
        red[t] = m;
        __syncthreads();
        #pragma unroll
        for (int s = 128; s > 0; s >>= 1) {
            if (t < s) red[t] = fmaxf(red[t], red[t + s]);
            __syncthreads();
        }
        m = red[0];
        __syncthreads();

        float sum = 0.f;
        for (int c = t; c < NN; c += 256) {
            float p = __expf(scores[c] - m);
            scores[c] = p;
            sum += p;
        }
        red[t] = sum;
        __syncthreads();
        #pragma unroll
        for (int s = 128; s > 0; s >>= 1) {
            if (t < s) red[t] += red[t + s];
            __syncthreads();
        }
        const float inv = 1.0f / red[0];
        __syncthreads();

        float o0 = 0.f, o1 = 0.f;
        for (int c = 0; c < NN; c++) {
            float p = scores[c];
            if (p != 0.f) {
                const float* vj = &g_v[(size_t)c * DD];
                o0 += p * vj[t];
                o1 += p * vj[t + 256];
            }
        }
        out[(size_t)i * DD + t]       = o0 * inv;
        out[(size_t)i * DD + t + 256] = o1 * inv;
    }
}

// ---------------- launch ---------------------------------------------------
extern "C" void kernel_launch(void* const* d_in, const int* in_sizes, int n_in,
                              void* d_out, int out_size)
{
    const float* x  = (const float*)d_in[0];
    const void*  ei = d_in[1];
    const float* Wq = (const float*)d_in[2];
    const float* bq = (const float*)d_in[3];
    const float* Wk = (const float*)d_in[4];
    const float* bk = (const float*)d_in[5];
    const float* Wv = (const float*)d_in[6];
    const float* bv = (const float*)d_in[7];
    float* out = (float*)d_out;
    const int E = in_sizes[1] / 2;

    float *pq, *pk, *pv;
    __half *pxh, *pxl;
    cudaGetSymbolAddress((void**)&pq, g_q);
    cudaGetSymbolAddress((void**)&pk, g_k);
    cudaGetSymbolAddress((void**)&pv, g_v);
    cudaGetSymbolAddress((void**)&pxh, g_xh);
    cudaGetSymbolAddress((void**)&pxl, g_xl);

    static cudaStream_t s2 = nullptr;
    static cudaEvent_t evFork = nullptr, evJoin = nullptr;
    if (!s2) {
        cudaStreamCreateWithFlags(&s2, cudaStreamNonBlocking);
        cudaEventCreateWithFlags(&evFork, cudaEventDisableTiming);
        cudaEventCreateWithFlags(&evJoin, cudaEventDisableTiming);
        cudaFuncSetAttribute(proj_f16_kernel,
                             cudaFuncAttributeMaxDynamicSharedMemorySize, 3 * PSTG);
    }

    // fork: adjacency chain on side stream
    cudaEventRecord(evFork, 0);
    cudaStreamWaitEvent(s2, evFork, 0);
    detect_kernel<<<1, 256, 0, s2>>>((const unsigned int*)ei);
    adj_zero_kernel<<<(NN * (NN / 32) + 255) / 256, 256, 0, s2>>>();
    adj_scatter_kernel<<<(E + 255) / 256, 256, 0, s2>>>(ei, E);
    cudaEventRecord(evJoin, s2);

    // main chain (noops shift the ncu -s 5 window onto proj)
    noop_kernel<<<1, 32>>>();
    noop_kernel<<<1, 32>>>();
    convh_kernel<<<(NN * DD / 4 + 255) / 256, 256>>>(x, pxh, pxl, NN * DD / 4);
    dim3 gT(DD / 32, DD / 32, 3);
    dim3 bT(32, 8);
    convTh3_kernel<<<gT, bT>>>(Wq, Wk, Wv);

    dim3 gProj(DD / 128, NN / 128, 3);
    proj_f16_kernel<<<gProj, 256, 3 * PSTG>>>(bq, pq, bk, pk, bv, pv);

    vmean1_kernel<<<64, 256>>>();
    vmean2_kernel<<<1, 256>>>();

    cudaStreamWaitEvent(0, evJoin, 0);
    spattn_kernel<<<NN, 256>>>(out);
}

// round 13
// speedup vs baseline: 1.6666x; 1.0609x over previous
#include <cuda_runtime.h>
#include <cuda_fp16.h>
#include <cstddef>
#include <cstdint>

#define NN 8192
#define DD 512
#define SCALE 0.04419417382415922f   // 1/sqrt(512)

// ---------------- scratch (static __device__ — no allocs allowed) ----------
__device__ float g_q[NN * DD];
__device__ float g_k[NN * DD];
__device__ float g_v[NN * DD];
__device__ __half g_vh[NN * DD];                      // fp16 copy of v for PV
__device__ float g_sc_spill[(size_t)NN * NN];         // worst-case scores
__device__ unsigned int g_adj[(size_t)NN * NN / 32];  // 8 MB adjacency bitmask
__device__ int g_is64;
__device__ __half g_xh[NN * DD];
__device__ __half g_xl[NN * DD];
__device__ __half g_wth[3 * DD * DD];
__device__ __half g_wtl[3 * DD * DD];

// ---------------- edge dtype detection -------------------------------------
__global__ void detect_kernel(const unsigned int* __restrict__ w) {
    __shared__ unsigned int red[256];
    unsigned int acc = 0;
    for (int i = threadIdx.x; i < 1024; i += 256) acc |= w[2 * i + 1];
    red[threadIdx.x] = acc;
    __syncthreads();
    #pragma unroll
    for (int s = 128; s > 0; s >>= 1) {
        if (threadIdx.x < s) red[threadIdx.x] |= red[threadIdx.x + s];
        __syncthreads();
    }
    if (threadIdx.x == 0) g_is64 = (red[0] == 0u) ? 1 : 0;
}

// ---------------- adjacency ------------------------------------------------
__global__ void adj_zero_kernel() {
    int i = blockIdx.x * blockDim.x + threadIdx.x;
    if (i < NN * (NN / 32)) g_adj[i] = 0u;
}

__global__ void adj_scatter_kernel(const void* __restrict__ ei, int E) {
    int e = blockIdx.x * blockDim.x + threadIdx.x;
    if (e >= E) return;
    int r, c;
    if (g_is64) {
        const long long* p = (const long long*)ei;
        r = (int)p[e];
        c = (int)p[(size_t)E + e];
    } else {
        const int* p = (const int*)ei;
        r = p[e];
        c = p[(size_t)E + e];
    }
    if ((unsigned)r >= NN || (unsigned)c >= NN) return;
    size_t bit = (size_t)r * NN + (size_t)c;
    atomicOr(&g_adj[bit >> 5], 1u << (bit & 31));
}

// ---------------- helpers ---------------------------------------------------
__device__ __forceinline__ void cp_async16(uint32_t smem_addr, const void* gptr) {
    asm volatile("cp.async.cg.shared.global [%0], [%1], 16;\n"
                 :: "r"(smem_addr), "l"(gptr));
}

__device__ __forceinline__ void ldsm_x4(uint32_t* r, uint32_t addr) {
    asm volatile("ldmatrix.sync.aligned.m8n8.x4.shared.b16 {%0,%1,%2,%3}, [%4];"
                 : "=r"(r[0]), "=r"(r[1]), "=r"(r[2]), "=r"(r[3]) : "r"(addr));
}

__device__ __forceinline__ void mma_f16(float* d, const uint32_t* a, uint32_t b0, uint32_t b1) {
    asm volatile(
        "mma.sync.aligned.m16n8k16.row.col.f32.f16.f16.f32 "
        "{%0,%1,%2,%3}, {%4,%5,%6,%7}, {%8,%9}, {%0,%1,%2,%3};\n"
        : "+f"(d[0]), "+f"(d[1]), "+f"(d[2]), "+f"(d[3])
        : "r"(a[0]), "r"(a[1]), "r"(a[2]), "r"(a[3]), "r"(b0), "r"(b1));
}

#define SWZ(row, chunk) ((((chunk) ^ (((row) >> 1) & 3)) << 4))

// ---------------- fused precompute: x hi/lo + all 3 W transposes ------------
// z == 0: elementwise split of x (blocks 0..4095)
// z == 1..3: 32x32 tiled transpose+split of Wq/Wk/Wv (blocks 0..255)
__global__ void convAll_kernel(const float* __restrict__ x,
                               const float* __restrict__ Wq,
                               const float* __restrict__ Wk,
                               const float* __restrict__ Wv) {
    const int z = blockIdx.z;
    if (z == 0) {
        int i = blockIdx.x * 256 + threadIdx.x;
        if (i >= NN * DD / 4) return;
        float4 v = ((const float4*)x)[i];
        __half h0 = __float2half_rn(v.x), h1 = __float2half_rn(v.y);
        __half h2 = __float2half_rn(v.z), h3 = __float2half_rn(v.w);
        __half l0 = __float2half_rn(v.x - __half2float(h0));
        __half l1 = __float2half_rn(v.y - __half2float(h1));
        __half l2 = __float2half_rn(v.z - __half2float(h2));
        __half l3 = __float2half_rn(v.w - __half2float(h3));
        __half2 hp[2] = {__halves2half2(h0, h1), __halves2half2(h2, h3)};
        __half2 lp[2] = {__halves2half2(l0, l1), __halves2half2(l2, l3)};
        ((float2*)g_xh)[i] = *(float2*)hp;
        ((float2*)g_xl)[i] = *(float2*)lp;
    } else {
        if (blockIdx.x >= 256) return;
        const float* W = (z == 1) ? Wq : (z == 2) ? Wk : Wv;
        __half* hi = g_wth + (size_t)(z - 1) * DD * DD;
        __half* lo = g_wtl + (size_t)(z - 1) * DD * DD;

        __shared__ float tile[32][33];
        const int k0 = (blockIdx.x & 15) * 32, n0 = (blockIdx.x >> 4) * 32;
        const int tx = threadIdx.x & 31, ty = threadIdx.x >> 5;   // 32 x 8
        #pragma unroll
        for (int r = 0; r < 32; r += 8)
            tile[ty + r][tx] = W[(size_t)(k0 + ty + r) * DD + n0 + tx];
        __syncthreads();
        #pragma unroll
        for (int r = 0; r < 32; r += 8) {
            float v = tile[tx][ty + r];
            __half h = __float2half_rn(v);
            hi[(size_t)(n0 + ty + r) * DD + k0 + tx] = h;
            lo[(size_t)(n0 + ty + r) * DD + k0 + tx] = __float2half_rn(v - __half2float(h));
        }
    }
}

// ---------------- QKV projection: fp16 mma.sync + ldmatrix, 3-stage ring ----
#define PSTG 32768

__global__ void __launch_bounds__(256, 2)
proj_f16_kernel(const float* __restrict__ bq, float* __restrict__ oq,
                const float* __restrict__ bk, float* __restrict__ ok,
                const float* __restrict__ bv, float* __restrict__ ov)
{
    extern __shared__ char dsm[];
    const uint32_t sbase = (uint32_t)__cvta_generic_to_shared(dsm);

    const int z = blockIdx.z;
    const float* bias = (z == 0) ? bq : (z == 1) ? bk : bv;
    float* C          = (z == 0) ? oq : (z == 1) ? ok : ov;

    const int t = threadIdx.x;
    const int lane = t & 31;
    const int wid  = t >> 5;
    const int warpRow = wid >> 1;
    const int warpCol = wid & 1;
    const int g  = lane >> 2;
    const int tg = lane & 3;
    const int bm = blockIdx.y;
    const int bn = blockIdx.x;

    const int lrow = t >> 1;
    const int lc0  = (t & 1) * 2;
    const __half* pAh = g_xh + (size_t)(bm * 128 + lrow) * DD;
    const __half* pAl = g_xl + (size_t)(bm * 128 + lrow) * DD;
    const __half* pBh = g_wth + (size_t)z * DD * DD + (size_t)(bn * 128 + lrow) * DD;
    const __half* pBl = g_wtl + (size_t)z * DD * DD + (size_t)(bn * 128 + lrow) * DD;

    const int rsel = (lane & 7) + ((lane >> 3) & 1) * 8;
    const int ksel = (lane >> 4) & 1;

    float d[2][8][4];
    #pragma unroll
    for (int mt = 0; mt < 2; mt++)
        #pragma unroll
        for (int nt = 0; nt < 8; nt++)
            #pragma unroll
            for (int r = 0; r < 4; r++) d[mt][nt][r] = 0.0f;

    #define LOADSTAGE(s, buf) do {                                            \
        const int _kh = (s) * 32;                                             \
        const uint32_t _sb = sbase + (buf) * PSTG;                            \
        _Pragma("unroll")                                                     \
        for (int _cc = 0; _cc < 2; _cc++) {                                   \
            const int _c = lc0 + _cc;                                         \
            const uint32_t _dst = lrow * 64 + SWZ(lrow, _c);                  \
            cp_async16(_sb + _dst,         pAh + _kh + _c * 8);               \
            cp_async16(_sb + 8192 + _dst,  pAl + _kh + _c * 8);               \
            cp_async16(_sb + 16384 + _dst, pBh + _kh + _c * 8);               \
            cp_async16(_sb + 24576 + _dst, pBl + _kh + _c * 8);               \
        }                                                                     \
        asm volatile("cp.async.commit_group;\n");                             \
    } while (0)

    LOADSTAGE(0, 0);
    LOADSTAGE(1, 1);

    const int NST = DD / 32;
    int buf = 0;
    for (int s = 0; s < NST; s++) {
        if (s < NST - 1) asm volatile("cp.async.wait_group 1;\n" ::: "memory");
        else             asm volatile("cp.async.wait_group 0;\n" ::: "memory");
        __syncthreads();

        if (s + 2 < NST) {
            int nb = buf + 2; if (nb >= 3) nb -= 3;
            LOADSTAGE(s + 2, nb);
        }

        const uint32_t sb = sbase + buf * PSTG;

        #pragma unroll
        for (int ks = 0; ks < 2; ks++) {
            const int chunk = ks * 2 + ksel;
            uint32_t ah[2][4], al[2][4];
            #pragma unroll
            for (int mt = 0; mt < 2; mt++) {
                const int rm = warpRow * 32 + mt * 16 + rsel;
                const uint32_t ao = sb + rm * 64 + SWZ(rm, chunk);
                ldsm_x4(ah[mt], ao);
                ldsm_x4(al[mt], ao + 8192);
            }
            #pragma unroll
            for (int half = 0; half < 2; half++) {
                uint32_t bh[2][4], bl[2][4];
                #pragma unroll
                for (int p = 0; p < 2; p++) {
                    const int rn = warpCol * 64 + (half * 2 + p) * 16 + rsel;
                    const uint32_t bo = sb + 16384 + rn * 64 + SWZ(rn, chunk);
                    ldsm_x4(bh[p], bo);
                    ldsm_x4(bl[p], bo + 8192);
                }
                #pragma unroll
                for (int p = 0; p < 2; p++)
                    #pragma unroll
                    for (int sub = 0; sub < 2; sub++)
                        #pragma unroll
                        for (int mt = 0; mt < 2; mt++)
                            mma_f16(d[mt][half * 4 + p * 2 + sub], ah[mt],
                                    bh[p][sub], bh[p][sub + 2]);
                #pragma unroll
                for (int p = 0; p < 2; p++)
                    #pragma unroll
                    for (int sub = 0; sub < 2; sub++)
                        #pragma unroll
                        for (int mt = 0; mt < 2; mt++)
                            mma_f16(d[mt][half * 4 + p * 2 + sub], ah[mt],
                                    bl[p][sub], bl[p][sub + 2]);
                #pragma unroll
                for (int p = 0; p < 2; p++)
                    #pragma unroll
                    for (int sub = 0; sub < 2; sub++)
                        #pragma unroll
                        for (int mt = 0; mt < 2; mt++)
                            mma_f16(d[mt][half * 4 + p * 2 + sub], al[mt],
                                    bh[p][sub], bh[p][sub + 2]);
            }
        }
        buf++; if (buf == 3) buf = 0;
    }

    #pragma unroll
    for (int mt = 0; mt < 2; mt++) {
        const int row = bm * 128 + warpRow * 32 + mt * 16 + g;
        #pragma unroll
        for (int nt = 0; nt < 8; nt++) {
            const int col = bn * 128 + warpCol * 64 + nt * 8 + 2 * tg;
            float2 bb = *(const float2*)&bias[col];
            float2 lo = {d[mt][nt][0] + bb.x, d[mt][nt][1] + bb.y};
            float2 hi = {d[mt][nt][2] + bb.x, d[mt][nt][3] + bb.y};
            *(float2*)&C[(size_t)row * DD + col]       = lo;
            *(float2*)&C[(size_t)(row + 8) * DD + col] = hi;
            if (z == 2) {
                *(__half2*)&g_vh[(size_t)row * DD + col] =
                    __floats2half2_rn(lo.x, lo.y);
                *(__half2*)&g_vh[(size_t)(row + 8) * DD + col] =
                    __floats2half2_rn(hi.x, hi.y);
            }
        }
    }
}

// ---------------- sparse attention: one block (256 thr) per row -----------
#define SC_CAP 1024

__global__ __launch_bounds__(256)
void spattn_kernel(float* __restrict__ out)
{
    const int i = blockIdx.x;
    const int t = threadIdx.x;
    const int lane = t & 31;
    const int wid  = t >> 5;

    __shared__ __align__(16) float qs[DD];
    __shared__ int   nbr[SC_CAP];
    __shared__ float sc[SC_CAP];
    __shared__ int   wsum[8];
    __shared__ float red[256];

    for (int d = t; d < DD; d += 256) qs[d] = g_q[(size_t)i * DD + d];

    // degree + exclusive offset via warp scans (2 barriers total)
    unsigned word = g_adj[i * 256 + t];
    int pc = __popc(word);
    int x = pc;
    #pragma unroll
    for (int o = 1; o < 32; o <<= 1) {
        int y = __shfl_up_sync(0xffffffffu, x, o);
        if (lane >= o) x += y;
    }
    if (lane == 31) wsum[wid] = x;
    __syncthreads();
    if (t < 8) {
        int sv = wsum[t];
        #pragma unroll
        for (int o = 1; o < 8; o <<= 1) {
            int y = __shfl_up_sync(0xffu, sv, o);
            if (t >= o) sv += y;
        }
        wsum[t] = sv;
    }
    __syncthreads();
    const int deg = wsum[7];
    const int base0 = (wid ? wsum[wid - 1] : 0) + x - pc;

    if (deg == 0) {
        // exact uniform-softmax fallback (probability ~1e-10; correctness only)
        float s0 = 0.f, s1 = 0.f;
        for (int r = 0; r < NN; r++) {
            float2 f = *(const float2*)&g_v[(size_t)r * DD + 2 * t];
            s0 += f.x; s1 += f.y;
        }
        float2 o = {s0 * (1.0f / NN), s1 * (1.0f / NN)};
        *(float2*)&out[(size_t)i * DD + 2 * t] = o;
        return;
    }

    if (deg <= SC_CAP) {
        {
            int base = base0;
            unsigned w = word;
            while (w) {
                int b = __ffs(w) - 1;
                w &= w - 1;
                nbr[base++] = t * 32 + b;
            }
        }
        __syncthreads();

        // SDDMM: 2 concurrent dots per warp
        for (int s = wid * 2; s < deg; s += 16) {
            const bool has2 = (s + 1 < deg);
            const float4* k0 = (const float4*)&g_k[(size_t)nbr[s] * DD];
            const float4* k1 = (const float4*)&g_k[(size_t)nbr[has2 ? s + 1 : s] * DD];
            const float4* q4 = (const float4*)qs;
            float acc0 = 0.f, acc1 = 0.f;
            #pragma unroll
            for (int d4 = lane; d4 < DD / 4; d4 += 32) {
                float4 qv  = q4[d4];
                float4 kv0 = k0[d4];
                float4 kv1 = k1[d4];
                acc0 += qv.x * kv0.x + qv.y * kv0.y + qv.z * kv0.z + qv.w * kv0.w;
                acc1 += qv.x * kv1.x + qv.y * kv1.y + qv.z * kv1.z + qv.w * kv1.w;
            }
            #pragma unroll
            for (int o = 16; o > 0; o >>= 1) {
                acc0 += __shfl_xor_sync(0xffffffffu, acc0, o);
                acc1 += __shfl_xor_sync(0xffffffffu, acc1, o);
            }
            if (lane == 0) {
                sc[s] = acc0 * SCALE;
                if (has2) sc[s + 1] = acc1 * SCALE;
            }
        }
        __syncthreads();

        float m = -3.4e38f;
        for (int s = t; s < deg; s += 256) m = fmaxf(m, sc[s]);
        red[t] = m;
        __syncthreads();
        #pragma unroll
        for (int s = 128; s > 0; s >>= 1) {
            if (t < s) red[t] = fmaxf(red[t], red[t + s]);
            __syncthreads();
        }
        m = red[0];
        __syncthreads();

        float sum = 0.f;
        for (int s = t; s < deg; s += 256) {
            float p = __expf(sc[s] - m);
            sc[s] = p;
            sum += p;
        }
        red[t] = sum;
        __syncthreads();
        #pragma unroll
        for (int s = 128; s > 0; s >>= 1) {
            if (t < s) red[t] += red[t + s];
            __syncthreads();
        }
        const float inv = 1.0f / red[0];
        __syncthreads();

        float o0 = 0.f, o1 = 0.f;
        int s = 0;
        for (; s + 3 < deg; s += 4) {
            __half2 v0 = *(const __half2*)&g_vh[(size_t)nbr[s]     * DD + 2 * t];
            __half2 v1 = *(const __half2*)&g_vh[(size_t)nbr[s + 1] * DD + 2 * t];
            __half2 v2 = *(const __half2*)&g_vh[(size_t)nbr[s + 2] * DD + 2 * t];
            __half2 v3 = *(const __half2*)&g_vh[(size_t)nbr[s + 3] * DD + 2 * t];
            float p0 = sc[s], p1 = sc[s + 1], p2 = sc[s + 2], p3 = sc[s + 3];
            float2 f0 = __half22float2(v0);
            float2 f1 = __half22float2(v1);
            float2 f2 = __half22float2(v2);
            float2 f3 = __half22float2(v3);
            o0 += p0 * f0.x + p1 * f1.x + p2 * f2.x + p3 * f3.x;
            o1 += p0 * f0.y + p1 * f1.y + p2 * f2.y + p3 * f3.y;
        }
        for (; s < deg; s++) {
            float p = sc[s];
            float2 f = __half22float2(*(const __half2*)&g_vh[(size_t)nbr[s] * DD + 2 * t]);
            o0 += p * f.x;
            o1 += p * f.y;
        }
        float2 o = {o0 * inv, o1 * inv};
        *(float2*)&out[(size_t)i * DD + 2 * t] = o;
    } else {
        float* scores = &g_sc_spill[(size_t)i * NN];
        for (int c = wid; c < NN; c += 8) {
            bool edge = (g_adj[i * 256 + (c >> 5)] >> (c & 31)) & 1u;
            float acc = 0.f;
            if (edge) {
                const float* kj = &g_k[(size_t)c * DD];
                for (int d = lane; d < DD; d += 32) acc += qs[d] * kj[d];
                #pragma unroll
                for (int o = 16; o > 0; o >>= 1) acc += __shfl_xor_sync(0xffffffffu, acc, o);
            }
            if (lane == 0) scores[c] = edge ? acc * SCALE : -3.4e38f;
        }
        __syncthreads();

        float m = -3.4e38f;
        for (int c = t; c < NN; c += 256) m = fmaxf(m, scores[c]);
        red[t] = m;
        __syncthreads();
        #pragma unroll
        for (int s = 128; s > 0; s >>= 1) {
            if (t < s) red[t] = fmaxf(red[t], red[t + s]);
            __syncthreads();
        }
        m = red[0];
        __syncthreads();

        float sum = 0.f;
        for (int c = t; c < NN; c += 256) {
            float p = __expf(scores[c] - m);
            scores[c] = p;
            sum += p;
        }
        red[t] = sum;
        __syncthreads();
        #pragma unroll
        for (int s = 128; s > 0; s >>= 1) {
            if (t < s) red[t] += red[t + s];
            __syncthreads();
        }
        const float inv = 1.0f / red[0];
        __syncthreads();

        float o0 = 0.f, o1 = 0.f;
        for (int c = 0; c < NN; c++) {
            float p = scores[c];
            if (p != 0.f) {
                const float* vj = &g_v[(size_t)c * DD];
                o0 += p * vj[t];
                o1 += p * vj[t + 256];
            }
        }
        out[(size_t)i * DD + t]       = o0 * inv;
        out[(size_t)i * DD + t + 256] = o1 * inv;
    }
}

// ---------------- launch ---------------------------------------------------
extern "C" void kernel_launch(void* const* d_in, const int* in_sizes, int n_in,
                              void* d_out, int out_size)
{
    const float* x  = (const float*)d_in[0];
    const void*  ei = d_in[1];
    const float* Wq = (const float*)d_in[2];
    const float* bq = (const float*)d_in[3];
    const float* Wk = (const float*)d_in[4];
    const float* bk = (const float*)d_in[5];
    const float* Wv = (const float*)d_in[6];
    const float* bv = (const float*)d_in[7];
    float* out = (float*)d_out;
    const int E = in_sizes[1] / 2;

    float *pq, *pk, *pv;
    cudaGetSymbolAddress((void**)&pq, g_q);
    cudaGetSymbolAddress((void**)&pk, g_k);
    cudaGetSymbolAddress((void**)&pv, g_v);

    static cudaStream_t s2 = nullptr;
    static cudaEvent_t evFork = nullptr, evJoin = nullptr;
    if (!s2) {
        cudaStreamCreateWithFlags(&s2, cudaStreamNonBlocking);
        cudaEventCreateWithFlags(&evFork, cudaEventDisableTiming);
        cudaEventCreateWithFlags(&evJoin, cudaEventDisableTiming);
        cudaFuncSetAttribute(proj_f16_kernel,
                             cudaFuncAttributeMaxDynamicSharedMemorySize, 3 * PSTG);
    }

    // fork: adjacency chain on side stream
    cudaEventRecord(evFork, 0);
    cudaStreamWaitEvent(s2, evFork, 0);
    detect_kernel<<<1, 256, 0, s2>>>((const unsigned int*)ei);
    adj_zero_kernel<<<(NN * (NN / 32) + 255) / 256, 256, 0, s2>>>();
    adj_scatter_kernel<<<(E + 255) / 256, 256, 0, s2>>>(ei, E);
    cudaEventRecord(evJoin, s2);

    // main chain: fused precompute -> proj -> spattn
    dim3 gConv(NN * DD / 4 / 256, 1, 4);
    convAll_kernel<<<gConv, 256>>>(x, Wq, Wk, Wv);

    dim3 gProj(DD / 128, NN / 128, 3);
    proj_f16_kernel<<<gProj, 256, 3 * PSTG>>>(bq, pq, bk, pk, bv, pv);

    cudaStreamWaitEvent(0, evJoin, 0);
    spattn_kernel<<<NN, 256>>>(out);
}